// round 4
// baseline (speedup 1.0000x reference)
#include <cuda_runtime.h>
#include <math.h>

#define BATCH 16
#define NC    2048
#define NT    2048
#define TG    2048
#define NBINS 128
#define RFAC  7.5f     // cutoff radius = RFAC * ls ; exp(-0.5*RFAC^2) < 1e-11
#define EPS   1e-8f

// Fixed binning: xc is uniform in [0, 128). Bin width = 1.0. Clamped => safe.
__device__ __forceinline__ int bin_fix(float x) {
    int b = (int)floorf(x);
    return min(NBINS - 1, max(0, b));
}

// ---------------- scratch (no allocs allowed) ----------------
__device__ float    g_minmax[2];                 // [lower, upper] (final)
__device__ float    g_plo[BATCH], g_phi[BATCH];  // per-batch partials
__device__ unsigned g_done = 0;                  // completion counter (self-resetting)
__device__ int      g_starts[BATCH * (NBINS + 1)];
__device__ float    g_sx[BATCH * NC];            // xc sorted by bin
__device__ float    g_sy[BATCH * NC];            // yc permuted alongside
__device__ float    g_h0[BATCH * TG];
__device__ float    g_h1[BATCH * TG];
__device__ float    g_fmu[BATCH * TG];
__device__ float    g_fsp[BATCH * TG];           // softplus(f_sigma)

// ---------------- K1: fused hist + scan + scatter + minmax ----------------
#define SPT 8   // NC / 256
__global__ __launch_bounds__(256) void sort_kernel(
    const float* __restrict__ xc, const float* __restrict__ yc,
    const float* __restrict__ xt) {
    __shared__ int scnt[NBINS];
    __shared__ int scur[NBINS];
    __shared__ int wsum[8];
    __shared__ float slo[8], shi[8];
    int b = blockIdx.x, tid = threadIdx.x;
    int lane = tid & 31, w = tid >> 5;

    for (int i = tid; i < NBINS; i += 256) scnt[i] = 0;
    __syncthreads();

    const float* xcb = xc + b * NC;
    const float* ycb = yc + b * NC;
    const float* xtb = xt + b * NT;
    float xv[SPT], yv[SPT];
    float lo = INFINITY, hi = -INFINITY;
    #pragma unroll
    for (int r = 0; r < SPT; r++) {
        int i = tid + r * 256;
        xv[r] = __ldg(&xcb[i]);
        yv[r] = __ldg(&ycb[i]);
    }
    #pragma unroll
    for (int r = 0; r < SPT; r++) {
        lo = fminf(lo, xv[r]); hi = fmaxf(hi, xv[r]);
        atomicAdd(&scnt[bin_fix(xv[r])], 1);
    }
    #pragma unroll
    for (int r = 0; r < SPT; r++) {
        float v = __ldg(&xtb[tid + r * 256]);
        lo = fminf(lo, v); hi = fmaxf(hi, v);
    }
    #pragma unroll
    for (int off = 16; off; off >>= 1) {
        lo = fminf(lo, __shfl_xor_sync(0xffffffffu, lo, off));
        hi = fmaxf(hi, __shfl_xor_sync(0xffffffffu, hi, off));
    }
    if (lane == 0) { slo[w] = lo; shi[w] = hi; }
    __syncthreads();

    // exclusive scan of the 128 bin counts (threads >= 128 carry 0)
    int c = (tid < NBINS) ? scnt[tid] : 0;
    int v = c;
    #pragma unroll
    for (int off = 1; off < 32; off <<= 1) {
        int n = __shfl_up_sync(0xffffffffu, v, off);
        if (lane >= off) v += n;
    }
    if (lane == 31) wsum[w] = v;
    __syncthreads();
    if (tid == 0) {
        int run = 0;
        #pragma unroll
        for (int k = 0; k < 8; k++) { int t = wsum[k]; wsum[k] = run; run += t; }
        float flo = slo[0], fhi = shi[0];
        #pragma unroll
        for (int k = 1; k < 8; k++) { flo = fminf(flo, slo[k]); fhi = fmaxf(fhi, shi[k]); }
        g_plo[b] = flo; g_phi[b] = fhi;
    }
    __syncthreads();
    if (tid < NBINS) {
        int excl = v - c + wsum[w];
        scur[tid] = excl;
        g_starts[b * (NBINS + 1) + tid] = excl;
    }
    if (tid == 0) g_starts[b * (NBINS + 1) + NBINS] = NC;
    __syncthreads();

    // scatter from registers via smem cursors
    #pragma unroll
    for (int r = 0; r < SPT; r++) {
        int pos = atomicAdd(&scur[bin_fix(xv[r])], 1);
        g_sx[b * NC + pos] = xv[r];
        g_sy[b * NC + pos] = yv[r];
    }

    // last block folds per-batch min/max partials into g_minmax
    __threadfence();
    if (tid == 0) {
        if (atomicAdd(&g_done, 1) == BATCH - 1) {
            __threadfence();
            volatile float* plo = g_plo;
            volatile float* phi = g_phi;
            float flo = INFINITY, fhi = -INFINITY;
            #pragma unroll
            for (int k = 0; k < BATCH; k++) {
                flo = fminf(flo, plo[k]); fhi = fmaxf(fhi, phi[k]);
            }
            g_minmax[0] = flo; g_minmax[1] = fhi;
            g_done = 0;
            __threadfence();
        }
    }
}

// ---------------- K2: psi stage — h0, h1 over truncated window ----------------
__global__ void psi_kernel(const float* __restrict__ pls,
                           const float* __restrict__ pos_) {
    int gw = (blockIdx.x * blockDim.x + threadIdx.x) >> 5;  // one warp per t-point
    int lane = threadIdx.x & 31;
    if (gw >= BATCH * TG) return;
    int b = gw >> 11, i = gw & (TG - 1);

    float lower = g_minmax[0], upper = g_minmax[1];
    float dt = (upper - lower) / (float)(TG - 1);
    float t = lower + i * dt;
    float ls = __ldg(pls), osv = __ldg(pos_);
    float inv2 = 0.5f / (ls * ls);
    float R = fabsf(ls) * RFAC;

    int blo = min(NBINS - 1, max(0, (int)floorf(t - R)));
    int bhi = min(NBINS - 1, max(0, (int)floorf(t + R)));
    int s = g_starts[b * (NBINS + 1) + blo];
    int e = g_starts[b * (NBINS + 1) + bhi + 1];

    const float* sx = g_sx + b * NC;
    const float* sy = g_sy + b * NC;
    float a0 = 0.f, a1 = 0.f;
    for (int k = s + lane; k < e; k += 32) {
        float xk = __ldg(&sx[k]);
        float yk = __ldg(&sy[k]);
        float d = t - xk;
        float ev = osv * __expf(-d * d * inv2);
        a0 += ev;
        a1 += ev * yk;
    }
    #pragma unroll
    for (int off = 16; off; off >>= 1) {
        a0 += __shfl_xor_sync(0xffffffffu, a0, off);
        a1 += __shfl_xor_sync(0xffffffffu, a1, off);
    }
    if (lane == 0) {
        g_h0[gw] = a0;
        g_h1[gw] = a1 / (a0 + EPS);
    }
}

// ---------------- K3: fused 4-layer conv chain (register-blocked) ----------------
#define T_TILE 128
#define HALO   8
#define CW     (T_TILE + 2 * HALO)  // 144
#define CNTH   256
#define P      8

// dynamic smem layout (floats):
//   s0: 3*CW | s1: 16*CW | s2: 32*CW | w1:240 | w2:2560 | w3:2560 | w4:160 | b:66
#define OFF_S0  0
#define OFF_S1  (OFF_S0 + 3 * CW)
#define OFF_S2  (OFF_S1 + 16 * CW)
#define OFF_W1  (OFF_S2 + 32 * CW)
#define OFF_W2  (OFF_W1 + 240)
#define OFF_W3  (OFF_W2 + 2560)
#define OFF_W4  (OFF_W3 + 2560)
#define OFF_B1  (OFF_W4 + 160)
#define OFF_B2  (OFF_B1 + 16)
#define OFF_B3  (OFF_B2 + 32)
#define OFF_B4  (OFF_B3 + 16)
#define SMEM_FLOATS (OFF_B4 + 2)
#define SMEM_BYTES  (SMEM_FLOATS * 4)

template <int NCO, int NCI, int LO>
__device__ __forceinline__ void conv_layer(const float* __restrict__ sin,
                                           float* __restrict__ sout,
                                           const float* __restrict__ sw,
                                           const float* __restrict__ sb,
                                           int p0, int tid) {
    const int nv = CW - 2 * LO;
    const int ng = (nv + P - 1) / P;
    for (int task = tid; task < NCO * ng; task += CNTH) {
        int co = task % NCO;
        int g = task / NCO;
        int ub = LO + g * P;
        int width = min(P, nv - g * P);
        float acc[P];
        #pragma unroll
        for (int j = 0; j < P; j++) acc[j] = 0.f;
        const float* wrow = sw + co * NCI * 5;
        for (int ci = 0; ci < NCI; ci++) {
            const float* srow = sin + ci * CW + ub - 2;
            float in[P + 4];
            #pragma unroll
            for (int i = 0; i < P + 4; i++)
                in[i] = (i < width + 4) ? srow[i] : 0.f;
            #pragma unroll
            for (int k = 0; k < 5; k++) {
                float wv = wrow[ci * 5 + k];
                #pragma unroll
                for (int j = 0; j < P; j++) acc[j] += wv * in[j + k];
            }
        }
        float bias = sb[co];
        #pragma unroll
        for (int j = 0; j < P; j++) {
            if (j < width) {
                int u = ub + j;
                int p = p0 + u;
                sout[co * CW + u] = (p >= 0 && p < TG) ? fmaxf(acc[j] + bias, 0.f) : 0.f;
            }
        }
    }
}

__global__ __launch_bounds__(CNTH) void conv_kernel(
    const float* __restrict__ w1, const float* __restrict__ b1,
    const float* __restrict__ w2, const float* __restrict__ b2,
    const float* __restrict__ w3, const float* __restrict__ b3,
    const float* __restrict__ w4, const float* __restrict__ b4) {
    extern __shared__ float dsm[];
    float* s0 = dsm + OFF_S0;
    float* s1 = dsm + OFF_S1;
    float* s2 = dsm + OFF_S2;

    const int tiles = TG / T_TILE;  // 16
    int b = blockIdx.x / tiles;
    int tile = blockIdx.x % tiles;
    int p0 = tile * T_TILE - HALO;
    int tid = threadIdx.x;

    // stage all weights + biases into smem
    for (int i = tid; i < 240; i += CNTH)  dsm[OFF_W1 + i] = __ldg(&w1[i]);
    for (int i = tid; i < 2560; i += CNTH) dsm[OFF_W2 + i] = __ldg(&w2[i]);
    for (int i = tid; i < 2560; i += CNTH) dsm[OFF_W3 + i] = __ldg(&w3[i]);
    for (int i = tid; i < 160; i += CNTH)  dsm[OFF_W4 + i] = __ldg(&w4[i]);
    if (tid < 16) dsm[OFF_B1 + tid] = __ldg(&b1[tid]);
    if (tid < 32) dsm[OFF_B2 + tid] = __ldg(&b2[tid]);
    if (tid >= 32 && tid < 48) dsm[OFF_B3 + tid - 32] = __ldg(&b3[tid - 32]);
    if (tid >= 48 && tid < 50) dsm[OFF_B4 + tid - 48] = __ldg(&b4[tid - 48]);

    float lower = g_minmax[0];
    float dt = (g_minmax[1] - lower) / (float)(TG - 1);

    // load input channels (t, h0, h1); zero outside [0, TG)
    for (int u = tid; u < CW; u += CNTH) {
        int p = p0 + u;
        bool in = (p >= 0 && p < TG);
        s0[0 * CW + u] = in ? (lower + p * dt) : 0.f;
        s0[1 * CW + u] = in ? g_h0[b * TG + p] : 0.f;
        s0[2 * CW + u] = in ? g_h1[b * TG + p] : 0.f;
    }
    __syncthreads();

    conv_layer<16, 3, 2>(s0, s1, dsm + OFF_W1, dsm + OFF_B1, p0, tid);
    __syncthreads();
    conv_layer<32, 16, 4>(s1, s2, dsm + OFF_W2, dsm + OFF_B2, p0, tid);
    __syncthreads();
    conv_layer<16, 32, 6>(s2, s1, dsm + OFF_W3, dsm + OFF_B3, p0, tid);
    __syncthreads();

    // layer 4: 16 -> 2, one thread per (co, position); co slow => weight broadcast
    {
        const float* sw4 = dsm + OFF_W4;
        const float* sb4 = dsm + OFF_B4;
        for (int task = tid; task < 2 * T_TILE; task += CNTH) {
            int co = task / T_TILE;
            int u = HALO + (task % T_TILE);
            float acc = sb4[co];
            #pragma unroll
            for (int ci = 0; ci < 16; ci++) {
                #pragma unroll
                for (int k = 0; k < 5; k++)
                    acc += sw4[(co * 16 + ci) * 5 + k] * s1[ci * CW + u - 2 + k];
            }
            int p = p0 + u;
            if (co == 0) {
                g_fmu[b * TG + p] = acc;
            } else {
                g_fsp[b * TG + p] = fmaxf(acc, 0.f) + log1pf(__expf(-fabsf(acc)));
            }
        }
    }
}

// ---------------- K4: rho stage — mu/sigma over truncated t-window ----------------
__global__ void rho_kernel(const float* __restrict__ xt,
                           const float* __restrict__ pls,
                           const float* __restrict__ pos_,
                           float* __restrict__ out) {
    int gw = (blockIdx.x * blockDim.x + threadIdx.x) >> 5;  // one warp per target
    int lane = threadIdx.x & 31;
    if (gw >= BATCH * NT) return;
    int b = gw >> 11;

    float lower = g_minmax[0];
    float dt = (g_minmax[1] - lower) / (float)(TG - 1);
    float x = __ldg(&xt[gw]);
    float ls = __ldg(pls), osv = __ldg(pos_);
    float inv2 = 0.5f / (ls * ls);
    float R = fabsf(ls) * RFAC;

    int ilo = max(0, (int)ceilf((x - R - lower) / dt));
    int ihi = min(TG - 1, (int)floorf((x + R - lower) / dt));

    const float* fm = g_fmu + b * TG;
    const float* fs = g_fsp + b * TG;
    float mu = 0.f, sg = 0.f;
    for (int i = ilo + lane; i <= ihi; i += 32) {
        float vm = __ldg(&fm[i]);
        float vs = __ldg(&fs[i]);
        float d = x - (lower + i * dt);
        float ev = osv * __expf(-d * d * inv2);
        mu += ev * vm;
        sg += ev * vs;
    }
    #pragma unroll
    for (int off = 16; off; off >>= 1) {
        mu += __shfl_xor_sync(0xffffffffu, mu, off);
        sg += __shfl_xor_sync(0xffffffffu, sg, off);
    }
    if (lane == 0) {
        out[gw * 2 + 0] = mu;
        out[gw * 2 + 1] = sg;
    }
}

// ---------------- launch ----------------
extern "C" void kernel_launch(void* const* d_in, const int* in_sizes, int n_in,
                              void* d_out, int out_size) {
    const float* xc = (const float*)d_in[0];
    const float* yc = (const float*)d_in[1];
    const float* xt = (const float*)d_in[2];
    const float* ls_psi = (const float*)d_in[3];
    const float* os_psi = (const float*)d_in[4];
    const float* ls_rho = (const float*)d_in[5];
    const float* os_rho = (const float*)d_in[6];
    const float* w1 = (const float*)d_in[7];
    const float* b1 = (const float*)d_in[8];
    const float* w2 = (const float*)d_in[9];
    const float* b2 = (const float*)d_in[10];
    const float* w3 = (const float*)d_in[11];
    const float* b3 = (const float*)d_in[12];
    const float* w4 = (const float*)d_in[13];
    const float* b4 = (const float*)d_in[14];
    float* out = (float*)d_out;

    static bool attr_set = false;
    if (!attr_set) {
        cudaFuncSetAttribute(conv_kernel,
                             cudaFuncAttributeMaxDynamicSharedMemorySize, SMEM_BYTES);
        attr_set = true;
    }

    sort_kernel<<<BATCH, 256>>>(xc, yc, xt);
    psi_kernel<<<(BATCH * TG) / 8, 256>>>(ls_psi, os_psi);
    conv_kernel<<<BATCH * (TG / T_TILE), CNTH, SMEM_BYTES>>>(w1, b1, w2, b2, w3, b3, w4, b4);
    rho_kernel<<<(BATCH * NT) / 8, 256>>>(xt, ls_rho, os_rho, out);
}

// round 5
// speedup vs baseline: 2.9251x; 2.9251x over previous
#include <cuda_runtime.h>
#include <math.h>

#define BATCH 16
#define NC    2048
#define NT    2048
#define TG    2048
#define NBINS 128
#define RFAC  5.5f     // cutoff radius = RFAC * ls ; exp(-0.5*5.5^2)=2.7e-7
#define EPS   1e-8f

// Fixed binning: xc is uniform in [0, 128). Bin width = 1.0. Clamped => safe.
__device__ __forceinline__ int bin_fix(float x) {
    int b = (int)floorf(x);
    return min(NBINS - 1, max(0, b));
}

// ---------------- scratch (no allocs allowed) ----------------
__device__ float    g_minmax[2];                 // [lower, upper] (final)
__device__ float    g_plo[BATCH], g_phi[BATCH];  // per-batch partials
__device__ unsigned g_done = 0;                  // completion counter (self-resetting)
__device__ int      g_starts[BATCH * (NBINS + 1)];
__device__ float    g_sx[BATCH * NC];            // xc sorted by bin
__device__ float    g_sy[BATCH * NC];            // yc permuted alongside
__device__ float    g_h0[BATCH * TG];
__device__ float    g_h1[BATCH * TG];
__device__ float    g_fmu[BATCH * TG];
__device__ float    g_fsp[BATCH * TG];           // softplus(f_sigma)

// ---------------- K1: fused hist + scan + scatter + minmax ----------------
#define SPT 8   // NC / 256
__global__ __launch_bounds__(256) void sort_kernel(
    const float* __restrict__ xc, const float* __restrict__ yc,
    const float* __restrict__ xt) {
    __shared__ int scnt[NBINS];
    __shared__ int scur[NBINS];
    __shared__ int wsum[8];
    __shared__ float slo[8], shi[8];
    int b = blockIdx.x, tid = threadIdx.x;
    int lane = tid & 31, w = tid >> 5;

    for (int i = tid; i < NBINS; i += 256) scnt[i] = 0;
    __syncthreads();

    const float* xcb = xc + b * NC;
    const float* ycb = yc + b * NC;
    const float* xtb = xt + b * NT;
    float xv[SPT], yv[SPT];
    float lo = INFINITY, hi = -INFINITY;
    #pragma unroll
    for (int r = 0; r < SPT; r++) {
        int i = tid + r * 256;
        xv[r] = __ldg(&xcb[i]);
        yv[r] = __ldg(&ycb[i]);
    }
    #pragma unroll
    for (int r = 0; r < SPT; r++) {
        lo = fminf(lo, xv[r]); hi = fmaxf(hi, xv[r]);
        atomicAdd(&scnt[bin_fix(xv[r])], 1);
    }
    #pragma unroll
    for (int r = 0; r < SPT; r++) {
        float v = __ldg(&xtb[tid + r * 256]);
        lo = fminf(lo, v); hi = fmaxf(hi, v);
    }
    #pragma unroll
    for (int off = 16; off; off >>= 1) {
        lo = fminf(lo, __shfl_xor_sync(0xffffffffu, lo, off));
        hi = fmaxf(hi, __shfl_xor_sync(0xffffffffu, hi, off));
    }
    if (lane == 0) { slo[w] = lo; shi[w] = hi; }
    __syncthreads();

    // exclusive scan of the 128 bin counts (threads >= 128 carry 0)
    int c = (tid < NBINS) ? scnt[tid] : 0;
    int v = c;
    #pragma unroll
    for (int off = 1; off < 32; off <<= 1) {
        int n = __shfl_up_sync(0xffffffffu, v, off);
        if (lane >= off) v += n;
    }
    if (lane == 31) wsum[w] = v;
    __syncthreads();
    if (tid == 0) {
        int run = 0;
        #pragma unroll
        for (int k = 0; k < 8; k++) { int t = wsum[k]; wsum[k] = run; run += t; }
        float flo = slo[0], fhi = shi[0];
        #pragma unroll
        for (int k = 1; k < 8; k++) { flo = fminf(flo, slo[k]); fhi = fmaxf(fhi, shi[k]); }
        g_plo[b] = flo; g_phi[b] = fhi;
    }
    __syncthreads();
    if (tid < NBINS) {
        int excl = v - c + wsum[w];
        scur[tid] = excl;
        g_starts[b * (NBINS + 1) + tid] = excl;
    }
    if (tid == 0) g_starts[b * (NBINS + 1) + NBINS] = NC;
    __syncthreads();

    // scatter from registers via smem cursors
    #pragma unroll
    for (int r = 0; r < SPT; r++) {
        int pos = atomicAdd(&scur[bin_fix(xv[r])], 1);
        g_sx[b * NC + pos] = xv[r];
        g_sy[b * NC + pos] = yv[r];
    }

    // last block folds per-batch min/max partials into g_minmax
    __threadfence();
    if (tid == 0) {
        if (atomicAdd(&g_done, 1) == BATCH - 1) {
            __threadfence();
            volatile float* plo = g_plo;
            volatile float* phi = g_phi;
            float flo = INFINITY, fhi = -INFINITY;
            #pragma unroll
            for (int k = 0; k < BATCH; k++) {
                flo = fminf(flo, plo[k]); fhi = fmaxf(fhi, phi[k]);
            }
            g_minmax[0] = flo; g_minmax[1] = fhi;
            g_done = 0;
            __threadfence();
        }
    }
}

// ---------------- K2: psi stage — h0, h1 over truncated window ----------------
__global__ void psi_kernel(const float* __restrict__ pls,
                           const float* __restrict__ pos_) {
    int gw = (blockIdx.x * blockDim.x + threadIdx.x) >> 5;  // one warp per t-point
    int lane = threadIdx.x & 31;
    if (gw >= BATCH * TG) return;
    int b = gw >> 11, i = gw & (TG - 1);

    float lower = g_minmax[0], upper = g_minmax[1];
    float dt = (upper - lower) / (float)(TG - 1);
    float t = lower + i * dt;
    float ls = __ldg(pls), osv = __ldg(pos_);
    float inv2 = 0.5f / (ls * ls);
    float R = fabsf(ls) * RFAC;

    int blo = min(NBINS - 1, max(0, (int)floorf(t - R)));
    int bhi = min(NBINS - 1, max(0, (int)floorf(t + R)));
    int s = g_starts[b * (NBINS + 1) + blo];
    int e = g_starts[b * (NBINS + 1) + bhi + 1];

    const float* sx = g_sx + b * NC;
    const float* sy = g_sy + b * NC;
    float a0 = 0.f, a1 = 0.f;
    for (int k = s + lane; k < e; k += 32) {
        float xk = __ldg(&sx[k]);
        float yk = __ldg(&sy[k]);
        float d = t - xk;
        float ev = osv * __expf(-d * d * inv2);
        a0 += ev;
        a1 += ev * yk;
    }
    #pragma unroll
    for (int off = 16; off; off >>= 1) {
        a0 += __shfl_xor_sync(0xffffffffu, a0, off);
        a1 += __shfl_xor_sync(0xffffffffu, a1, off);
    }
    if (lane == 0) {
        g_h0[gw] = a0;
        g_h1[gw] = a1 / (a0 + EPS);
    }
}

// ---------------- K3: fused 4-layer conv chain (P=4 x Q=4 register-blocked) ----------------
#define T_TILE 128
#define HALO   8
#define CW     (T_TILE + 2 * HALO)  // 144
#define CWP    152                  // padded row stride (floats), mult of 4
#define CNTH   256

// dynamic smem layout (floats), all offsets multiples of 4 (16B aligned)
#define OFF_S0  0
#define OFF_S1  (OFF_S0 + 3 * CWP)     // 456
#define OFF_S2  (OFF_S1 + 16 * CWP)    // 2888
#define OFF_W1  (OFF_S2 + 32 * CWP)    // 7752
#define OFF_W2  (OFF_W1 + 240)         // 7992
#define OFF_W3  (OFF_W2 + 2560)        // 10552
#define OFF_W4  (OFF_W3 + 2560)        // 13112
#define OFF_B1  (OFF_W4 + 160)         // 13272
#define OFF_B2  (OFF_B1 + 16)
#define OFF_B3  (OFF_B2 + 32)
#define OFF_B4  (OFF_B3 + 16)
#define SMEM_FLOATS (OFF_B4 + 4)
#define SMEM_BYTES  (SMEM_FLOATS * 4)

// One layer: NCO output ch, NCI input ch, LO = valid-window offset.
// Thread task = 4 consecutive positions x 4 output channels.
// Lanes: position-group fast => weight reads broadcast, input float4 reads
// lane-contiguous (16B stride, conflict-free), float2 stores conflict-free.
template <int NCO, int NCI, int LO>
__device__ __forceinline__ void conv_layer(const float* __restrict__ sin,
                                           float* __restrict__ sout,
                                           const float4* __restrict__ sw4,
                                           const float* __restrict__ sb,
                                           int p0, int tid) {
    constexpr int nv = CW - 2 * LO;         // 140 / 136 / 132 (all % 4 == 0)
    constexpr int ngp = nv / 4;
    constexpr int ncog = NCO / 4;
    constexpr int off = (LO - 2) & 3;       // 0 / 2 / 0

    for (int task = tid; task < ncog * ngp; task += CNTH) {
        int gp = task % ngp;
        int cog = task / ngp;
        int u0 = LO + gp * 4;
        int base = u0 - 2 - off;            // 16B aligned, >= 0

        float acc[4][4];
        #pragma unroll
        for (int q = 0; q < 4; q++)
            #pragma unroll
            for (int j = 0; j < 4; j++) acc[q][j] = 0.f;

        for (int ci = 0; ci < NCI; ci++) {
            const float4* sr = reinterpret_cast<const float4*>(sin + ci * CWP + base);
            float4 A = sr[0], B = sr[1], C = sr[2];
            float win[12] = {A.x, A.y, A.z, A.w, B.x, B.y, B.z, B.w,
                             C.x, C.y, C.z, C.w};
            #pragma unroll
            for (int k = 0; k < 5; k++) {
                float4 wv = sw4[(cog * NCI + ci) * 5 + k];
                #pragma unroll
                for (int j = 0; j < 4; j++) {
                    float xv = win[off + k + j];
                    acc[0][j] = fmaf(wv.x, xv, acc[0][j]);
                    acc[1][j] = fmaf(wv.y, xv, acc[1][j]);
                    acc[2][j] = fmaf(wv.z, xv, acc[2][j]);
                    acc[3][j] = fmaf(wv.w, xv, acc[3][j]);
                }
            }
        }
        #pragma unroll
        for (int q = 0; q < 4; q++) {
            int co = cog * 4 + q;
            float bias = sb[co];
            float v[4];
            #pragma unroll
            for (int j = 0; j < 4; j++) {
                int p = p0 + u0 + j;
                v[j] = (p >= 0 && p < TG) ? fmaxf(acc[q][j] + bias, 0.f) : 0.f;
            }
            float2* so = reinterpret_cast<float2*>(sout + co * CWP + u0);
            so[0] = make_float2(v[0], v[1]);
            so[1] = make_float2(v[2], v[3]);
        }
    }
}

__global__ __launch_bounds__(CNTH) void conv_kernel(
    const float* __restrict__ w1, const float* __restrict__ b1,
    const float* __restrict__ w2, const float* __restrict__ b2,
    const float* __restrict__ w3, const float* __restrict__ b3,
    const float* __restrict__ w4, const float* __restrict__ b4) {
    extern __shared__ float dsm[];
    float* s0 = dsm + OFF_S0;
    float* s1 = dsm + OFF_S1;
    float* s2 = dsm + OFF_S2;

    const int tiles = TG / T_TILE;  // 16
    int b = blockIdx.x / tiles;
    int tile = blockIdx.x % tiles;
    int p0 = tile * T_TILE - HALO;
    int tid = threadIdx.x;

    // stage weights, re-packed to [cog][ci][k][coq] so a thread's 4 co-weights
    // are a single broadcast LDS.128
    for (int i = tid; i < 240; i += CNTH) {   // w1: NCI=3 -> per-cog 60
        int co = i / 15, r = i % 15;
        dsm[OFF_W1 + (co >> 2) * 60 + r * 4 + (co & 3)] = __ldg(&w1[i]);
    }
    for (int i = tid; i < 2560; i += CNTH) {  // w2: NCI=16 -> per-cog 320
        int co = i / 80, r = i % 80;
        dsm[OFF_W2 + (co >> 2) * 320 + r * 4 + (co & 3)] = __ldg(&w2[i]);
    }
    for (int i = tid; i < 2560; i += CNTH) {  // w3: NCI=32 -> per-cog 640
        int co = i / 160, r = i % 160;
        dsm[OFF_W3 + (co >> 2) * 640 + r * 4 + (co & 3)] = __ldg(&w3[i]);
    }
    for (int i = tid; i < 160; i += CNTH)  dsm[OFF_W4 + i] = __ldg(&w4[i]);  // plain
    if (tid < 16) dsm[OFF_B1 + tid] = __ldg(&b1[tid]);
    if (tid < 32) dsm[OFF_B2 + tid] = __ldg(&b2[tid]);
    if (tid >= 32 && tid < 48) dsm[OFF_B3 + tid - 32] = __ldg(&b3[tid - 32]);
    if (tid >= 48 && tid < 50) dsm[OFF_B4 + tid - 48] = __ldg(&b4[tid - 48]);

    float lower = g_minmax[0];
    float dt = (g_minmax[1] - lower) / (float)(TG - 1);

    // load input channels (t, h0, h1); zero outside [0, TG)
    for (int u = tid; u < CW; u += CNTH) {
        int p = p0 + u;
        bool in = (p >= 0 && p < TG);
        s0[0 * CWP + u] = in ? (lower + p * dt) : 0.f;
        s0[1 * CWP + u] = in ? g_h0[b * TG + p] : 0.f;
        s0[2 * CWP + u] = in ? g_h1[b * TG + p] : 0.f;
    }
    __syncthreads();

    conv_layer<16, 3, 2>(s0, s1, reinterpret_cast<const float4*>(dsm + OFF_W1),
                         dsm + OFF_B1, p0, tid);
    __syncthreads();
    conv_layer<32, 16, 4>(s1, s2, reinterpret_cast<const float4*>(dsm + OFF_W2),
                          dsm + OFF_B2, p0, tid);
    __syncthreads();
    conv_layer<16, 32, 6>(s2, s1, reinterpret_cast<const float4*>(dsm + OFF_W3),
                          dsm + OFF_B3, p0, tid);
    __syncthreads();

    // layer 4: 16 -> 2; one thread per (co, position), position fast within co
    // => input LDS consecutive (conflict-free), weight LDS uniform (broadcast)
    {
        const float* sw4 = dsm + OFF_W4;
        const float* sb4 = dsm + OFF_B4;
        int co = tid >> 7;              // 0..1
        int u = HALO + (tid & 127);     // 8..135
        float acc = sb4[co];
        #pragma unroll
        for (int ci = 0; ci < 16; ci++) {
            #pragma unroll
            for (int k = 0; k < 5; k++)
                acc = fmaf(sw4[(co * 16 + ci) * 5 + k], s1[ci * CWP + u - 2 + k], acc);
        }
        int p = p0 + u;                 // always in [0, TG)
        if (co == 0) {
            g_fmu[b * TG + p] = acc;
        } else {
            g_fsp[b * TG + p] = fmaxf(acc, 0.f) + log1pf(__expf(-fabsf(acc)));
        }
    }
}

// ---------------- K4: rho stage — mu/sigma over truncated t-window ----------------
__global__ void rho_kernel(const float* __restrict__ xt,
                           const float* __restrict__ pls,
                           const float* __restrict__ pos_,
                           float* __restrict__ out) {
    int gw = (blockIdx.x * blockDim.x + threadIdx.x) >> 5;  // one warp per target
    int lane = threadIdx.x & 31;
    if (gw >= BATCH * NT) return;
    int b = gw >> 11;

    float lower = g_minmax[0];
    float dt = (g_minmax[1] - lower) / (float)(TG - 1);
    float x = __ldg(&xt[gw]);
    float ls = __ldg(pls), osv = __ldg(pos_);
    float inv2 = 0.5f / (ls * ls);
    float R = fabsf(ls) * RFAC;

    int ilo = max(0, (int)ceilf((x - R - lower) / dt));
    int ihi = min(TG - 1, (int)floorf((x + R - lower) / dt));

    const float* fm = g_fmu + b * TG;
    const float* fs = g_fsp + b * TG;
    float mu = 0.f, sg = 0.f;
    for (int i = ilo + lane; i <= ihi; i += 32) {
        float vm = __ldg(&fm[i]);
        float vs = __ldg(&fs[i]);
        float d = x - (lower + i * dt);
        float ev = osv * __expf(-d * d * inv2);
        mu += ev * vm;
        sg += ev * vs;
    }
    #pragma unroll
    for (int off = 16; off; off >>= 1) {
        mu += __shfl_xor_sync(0xffffffffu, mu, off);
        sg += __shfl_xor_sync(0xffffffffu, sg, off);
    }
    if (lane == 0) {
        out[gw * 2 + 0] = mu;
        out[gw * 2 + 1] = sg;
    }
}

// ---------------- launch ----------------
extern "C" void kernel_launch(void* const* d_in, const int* in_sizes, int n_in,
                              void* d_out, int out_size) {
    const float* xc = (const float*)d_in[0];
    const float* yc = (const float*)d_in[1];
    const float* xt = (const float*)d_in[2];
    const float* ls_psi = (const float*)d_in[3];
    const float* os_psi = (const float*)d_in[4];
    const float* ls_rho = (const float*)d_in[5];
    const float* os_rho = (const float*)d_in[6];
    const float* w1 = (const float*)d_in[7];
    const float* b1 = (const float*)d_in[8];
    const float* w2 = (const float*)d_in[9];
    const float* b2 = (const float*)d_in[10];
    const float* w3 = (const float*)d_in[11];
    const float* b3 = (const float*)d_in[12];
    const float* w4 = (const float*)d_in[13];
    const float* b4 = (const float*)d_in[14];
    float* out = (float*)d_out;

    cudaFuncSetAttribute(conv_kernel,
                         cudaFuncAttributeMaxDynamicSharedMemorySize, SMEM_BYTES);

    sort_kernel<<<BATCH, 256>>>(xc, yc, xt);
    psi_kernel<<<(BATCH * TG) / 8, 256>>>(ls_psi, os_psi);
    conv_kernel<<<BATCH * (TG / T_TILE), CNTH, SMEM_BYTES>>>(w1, b1, w2, b2, w3, b3, w4, b4);
    rho_kernel<<<(BATCH * NT) / 8, 256>>>(xt, ls_rho, os_rho, out);
}

// round 6
// speedup vs baseline: 3.1460x; 1.0755x over previous
#include <cuda_runtime.h>
#include <math.h>

#define BATCH 16
#define NC    2048
#define NT    2048
#define TG    2048
#define NBINS 128
#define RFAC  4.0f     // truncation tail ~ erfc(4/sqrt2) = 6.6e-5 << 1e-3 gate
#define EPS   1e-8f

// Fixed binning: xc is uniform in [0, 128). Bin width = 1.0. Clamped => safe.
__device__ __forceinline__ int bin_fix(float x) {
    int b = (int)floorf(x);
    return min(NBINS - 1, max(0, b));
}

// ---------------- scratch (no allocs allowed) ----------------
__device__ float    g_minmax[2];                 // [lower, upper] (final)
__device__ float    g_plo[BATCH], g_phi[BATCH];  // per-batch partials
__device__ unsigned g_done = 0;                  // completion counter (self-resetting)
__device__ int      g_starts[BATCH * (NBINS + 1)];
__device__ float2   g_sxy[BATCH * NC];           // (xc, yc) sorted by bin
__device__ float2   g_h[BATCH * TG];             // (h0, h1)
__device__ float2   g_f[BATCH * TG];             // (f_mu, softplus(f_sigma))

// ---------------- K1: fused hist + scan + scatter + minmax ----------------
#define SPT 8   // NC / 256
__global__ __launch_bounds__(256) void sort_kernel(
    const float* __restrict__ xc, const float* __restrict__ yc,
    const float* __restrict__ xt) {
    __shared__ int scnt[NBINS];
    __shared__ int scur[NBINS];
    __shared__ int wsum[8];
    __shared__ float slo[8], shi[8];
    int b = blockIdx.x, tid = threadIdx.x;
    int lane = tid & 31, w = tid >> 5;

    for (int i = tid; i < NBINS; i += 256) scnt[i] = 0;
    __syncthreads();

    const float* xcb = xc + b * NC;
    const float* ycb = yc + b * NC;
    const float* xtb = xt + b * NT;
    float xv[SPT], yv[SPT];
    float lo = INFINITY, hi = -INFINITY;
    #pragma unroll
    for (int r = 0; r < SPT; r++) {
        int i = tid + r * 256;
        xv[r] = __ldg(&xcb[i]);
        yv[r] = __ldg(&ycb[i]);
    }
    #pragma unroll
    for (int r = 0; r < SPT; r++) {
        lo = fminf(lo, xv[r]); hi = fmaxf(hi, xv[r]);
        atomicAdd(&scnt[bin_fix(xv[r])], 1);
    }
    #pragma unroll
    for (int r = 0; r < SPT; r++) {
        float v = __ldg(&xtb[tid + r * 256]);
        lo = fminf(lo, v); hi = fmaxf(hi, v);
    }
    #pragma unroll
    for (int off = 16; off; off >>= 1) {
        lo = fminf(lo, __shfl_xor_sync(0xffffffffu, lo, off));
        hi = fmaxf(hi, __shfl_xor_sync(0xffffffffu, hi, off));
    }
    if (lane == 0) { slo[w] = lo; shi[w] = hi; }
    __syncthreads();

    // exclusive scan of the 128 bin counts (threads >= 128 carry 0)
    int c = (tid < NBINS) ? scnt[tid] : 0;
    int v = c;
    #pragma unroll
    for (int off = 1; off < 32; off <<= 1) {
        int n = __shfl_up_sync(0xffffffffu, v, off);
        if (lane >= off) v += n;
    }
    if (lane == 31) wsum[w] = v;
    __syncthreads();
    if (tid == 0) {
        int run = 0;
        #pragma unroll
        for (int k = 0; k < 8; k++) { int t = wsum[k]; wsum[k] = run; run += t; }
        float flo = slo[0], fhi = shi[0];
        #pragma unroll
        for (int k = 1; k < 8; k++) { flo = fminf(flo, slo[k]); fhi = fmaxf(fhi, shi[k]); }
        g_plo[b] = flo; g_phi[b] = fhi;
    }
    __syncthreads();
    if (tid < NBINS) {
        int excl = v - c + wsum[w];
        scur[tid] = excl;
        g_starts[b * (NBINS + 1) + tid] = excl;
    }
    if (tid == 0) g_starts[b * (NBINS + 1) + NBINS] = NC;
    __syncthreads();

    // scatter from registers via smem cursors
    #pragma unroll
    for (int r = 0; r < SPT; r++) {
        int pos = atomicAdd(&scur[bin_fix(xv[r])], 1);
        g_sxy[b * NC + pos] = make_float2(xv[r], yv[r]);
    }

    // last block folds per-batch min/max partials into g_minmax
    __threadfence();
    if (tid == 0) {
        if (atomicAdd(&g_done, 1) == BATCH - 1) {
            __threadfence();
            volatile float* plo = g_plo;
            volatile float* phi = g_phi;
            float flo = INFINITY, fhi = -INFINITY;
            #pragma unroll
            for (int k = 0; k < BATCH; k++) {
                flo = fminf(flo, plo[k]); fhi = fmaxf(fhi, phi[k]);
            }
            g_minmax[0] = flo; g_minmax[1] = fhi;
            g_done = 0;
            __threadfence();
        }
    }
}

// ---------------- K2: psi stage — h0, h1 over truncated window ----------------
__global__ void psi_kernel(const float* __restrict__ pls,
                           const float* __restrict__ pos_) {
    int gw = (blockIdx.x * blockDim.x + threadIdx.x) >> 5;  // one warp per t-point
    int lane = threadIdx.x & 31;
    if (gw >= BATCH * TG) return;
    int b = gw >> 11, i = gw & (TG - 1);

    float lower = g_minmax[0], upper = g_minmax[1];
    float dt = (upper - lower) / (float)(TG - 1);
    float t = lower + i * dt;
    float ls = __ldg(pls), osv = __ldg(pos_);
    float inv2 = 0.5f / (ls * ls);
    float R = fabsf(ls) * RFAC;

    int blo = min(NBINS - 1, max(0, (int)floorf(t - R)));
    int bhi = min(NBINS - 1, max(0, (int)floorf(t + R)));
    int s = g_starts[b * (NBINS + 1) + blo];
    int e = g_starts[b * (NBINS + 1) + bhi + 1];

    const float2* sxy = g_sxy + b * NC;
    float a0 = 0.f, a1 = 0.f;
    for (int k = s + lane; k < e; k += 32) {
        float2 xy = __ldg(&sxy[k]);
        float d = t - xy.x;
        float ev = __expf(-d * d * inv2);
        a0 += ev;
        a1 += ev * xy.y;
    }
    #pragma unroll
    for (int off = 16; off; off >>= 1) {
        a0 += __shfl_xor_sync(0xffffffffu, a0, off);
        a1 += __shfl_xor_sync(0xffffffffu, a1, off);
    }
    if (lane == 0) {
        a0 *= osv; a1 *= osv;
        g_h[gw] = make_float2(a0, a1 / (a0 + EPS));
    }
}

// ---------------- K3: fused 4-layer conv chain (P=4 x Q=4 register-blocked) ----------------
#define T_TILE 128
#define HALO   8
#define CW     (T_TILE + 2 * HALO)  // 144
#define CWP    152                  // padded row stride (floats), mult of 4
#define CNTH   256

// dynamic smem layout (floats), all offsets multiples of 4 (16B aligned)
#define OFF_S0  0
#define OFF_S1  (OFF_S0 + 3 * CWP)     // 456
#define OFF_S2  (OFF_S1 + 16 * CWP)    // 2888
#define OFF_W1  (OFF_S2 + 32 * CWP)    // 7752
#define OFF_W2  (OFF_W1 + 240)         // 7992
#define OFF_W3  (OFF_W2 + 2560)        // 10552
#define OFF_W4  (OFF_W3 + 2560)        // 13112
#define OFF_B1  (OFF_W4 + 160)         // 13272
#define OFF_B2  (OFF_B1 + 16)
#define OFF_B3  (OFF_B2 + 32)
#define OFF_B4  (OFF_B3 + 16)
#define SMEM_FLOATS (OFF_B4 + 4)
#define SMEM_BYTES  (SMEM_FLOATS * 4)

// One layer: NCO output ch, NCI input ch, LO = valid-window offset.
// Thread task = 4 consecutive positions x 4 output channels.
// Lanes: position-group fast => weight reads broadcast, input float4 reads
// lane-contiguous (16B stride, conflict-free), float2 stores conflict-free.
template <int NCO, int NCI, int LO>
__device__ __forceinline__ void conv_layer(const float* __restrict__ sin,
                                           float* __restrict__ sout,
                                           const float4* __restrict__ sw4,
                                           const float* __restrict__ sb,
                                           int p0, int tid) {
    constexpr int nv = CW - 2 * LO;         // 140 / 136 / 132 (all % 4 == 0)
    constexpr int ngp = nv / 4;
    constexpr int ncog = NCO / 4;
    constexpr int off = (LO - 2) & 3;       // 0 / 2 / 0

    for (int task = tid; task < ncog * ngp; task += CNTH) {
        int gp = task % ngp;
        int cog = task / ngp;
        int u0 = LO + gp * 4;
        int base = u0 - 2 - off;            // 16B aligned, >= 0

        float acc[4][4];
        #pragma unroll
        for (int q = 0; q < 4; q++)
            #pragma unroll
            for (int j = 0; j < 4; j++) acc[q][j] = 0.f;

        for (int ci = 0; ci < NCI; ci++) {
            const float4* sr = reinterpret_cast<const float4*>(sin + ci * CWP + base);
            float4 A = sr[0], B = sr[1], C = sr[2];
            float win[12] = {A.x, A.y, A.z, A.w, B.x, B.y, B.z, B.w,
                             C.x, C.y, C.z, C.w};
            #pragma unroll
            for (int k = 0; k < 5; k++) {
                float4 wv = sw4[(cog * NCI + ci) * 5 + k];
                #pragma unroll
                for (int j = 0; j < 4; j++) {
                    float xv = win[off + k + j];
                    acc[0][j] = fmaf(wv.x, xv, acc[0][j]);
                    acc[1][j] = fmaf(wv.y, xv, acc[1][j]);
                    acc[2][j] = fmaf(wv.z, xv, acc[2][j]);
                    acc[3][j] = fmaf(wv.w, xv, acc[3][j]);
                }
            }
        }
        #pragma unroll
        for (int q = 0; q < 4; q++) {
            int co = cog * 4 + q;
            float bias = sb[co];
            float v[4];
            #pragma unroll
            for (int j = 0; j < 4; j++) {
                int p = p0 + u0 + j;
                v[j] = (p >= 0 && p < TG) ? fmaxf(acc[q][j] + bias, 0.f) : 0.f;
            }
            float2* so = reinterpret_cast<float2*>(sout + co * CWP + u0);
            so[0] = make_float2(v[0], v[1]);
            so[1] = make_float2(v[2], v[3]);
        }
    }
}

__global__ __launch_bounds__(CNTH) void conv_kernel(
    const float* __restrict__ w1, const float* __restrict__ b1,
    const float* __restrict__ w2, const float* __restrict__ b2,
    const float* __restrict__ w3, const float* __restrict__ b3,
    const float* __restrict__ w4, const float* __restrict__ b4) {
    extern __shared__ float dsm[];
    float* s0 = dsm + OFF_S0;
    float* s1 = dsm + OFF_S1;
    float* s2 = dsm + OFF_S2;

    const int tiles = TG / T_TILE;  // 16
    int b = blockIdx.x / tiles;
    int tile = blockIdx.x % tiles;
    int p0 = tile * T_TILE - HALO;
    int tid = threadIdx.x;

    // stage weights, re-packed to [cog][ci][k][coq] so a thread's 4 co-weights
    // are a single broadcast LDS.128
    for (int i = tid; i < 240; i += CNTH) {   // w1: NCI=3 -> per-cog 60
        int co = i / 15, r = i % 15;
        dsm[OFF_W1 + (co >> 2) * 60 + r * 4 + (co & 3)] = __ldg(&w1[i]);
    }
    for (int i = tid; i < 2560; i += CNTH) {  // w2: NCI=16 -> per-cog 320
        int co = i / 80, r = i % 80;
        dsm[OFF_W2 + (co >> 2) * 320 + r * 4 + (co & 3)] = __ldg(&w2[i]);
    }
    for (int i = tid; i < 2560; i += CNTH) {  // w3: NCI=32 -> per-cog 640
        int co = i / 160, r = i % 160;
        dsm[OFF_W3 + (co >> 2) * 640 + r * 4 + (co & 3)] = __ldg(&w3[i]);
    }
    for (int i = tid; i < 160; i += CNTH)  dsm[OFF_W4 + i] = __ldg(&w4[i]);  // plain
    if (tid < 16) dsm[OFF_B1 + tid] = __ldg(&b1[tid]);
    if (tid < 32) dsm[OFF_B2 + tid] = __ldg(&b2[tid]);
    if (tid >= 32 && tid < 48) dsm[OFF_B3 + tid - 32] = __ldg(&b3[tid - 32]);
    if (tid >= 48 && tid < 50) dsm[OFF_B4 + tid - 48] = __ldg(&b4[tid - 48]);

    float lower = g_minmax[0];
    float dt = (g_minmax[1] - lower) / (float)(TG - 1);

    // load input channels (t, h0, h1); zero outside [0, TG)
    for (int u = tid; u < CW; u += CNTH) {
        int p = p0 + u;
        bool in = (p >= 0 && p < TG);
        float2 h = in ? g_h[b * TG + p] : make_float2(0.f, 0.f);
        s0[0 * CWP + u] = in ? (lower + p * dt) : 0.f;
        s0[1 * CWP + u] = h.x;
        s0[2 * CWP + u] = h.y;
    }
    __syncthreads();

    conv_layer<16, 3, 2>(s0, s1, reinterpret_cast<const float4*>(dsm + OFF_W1),
                         dsm + OFF_B1, p0, tid);
    __syncthreads();
    conv_layer<32, 16, 4>(s1, s2, reinterpret_cast<const float4*>(dsm + OFF_W2),
                          dsm + OFF_B2, p0, tid);
    __syncthreads();
    conv_layer<16, 32, 6>(s2, s1, reinterpret_cast<const float4*>(dsm + OFF_W3),
                          dsm + OFF_B3, p0, tid);
    __syncthreads();

    // layer 4: 16 -> 2; one thread per position computes BOTH channels,
    // enabling a single float2 store (and float2 loads in rho).
    if (tid < T_TILE) {
        const float* sw4 = dsm + OFF_W4;
        const float* sb4 = dsm + OFF_B4;
        int u = HALO + tid;
        float acc0 = sb4[0], acc1 = sb4[1];
        #pragma unroll
        for (int ci = 0; ci < 16; ci++) {
            #pragma unroll
            for (int k = 0; k < 5; k++) {
                float xv = s1[ci * CWP + u - 2 + k];
                acc0 = fmaf(sw4[(0 * 16 + ci) * 5 + k], xv, acc0);
                acc1 = fmaf(sw4[(1 * 16 + ci) * 5 + k], xv, acc1);
            }
        }
        int p = p0 + u;                 // always in [0, TG)
        float sp = fmaxf(acc1, 0.f) + log1pf(__expf(-fabsf(acc1)));
        g_f[b * TG + p] = make_float2(acc0, sp);
    }
}

// ---------------- K4: rho stage — mu/sigma over truncated t-window ----------------
__global__ void rho_kernel(const float* __restrict__ xt,
                           const float* __restrict__ pls,
                           const float* __restrict__ pos_,
                           float* __restrict__ out) {
    int gw = (blockIdx.x * blockDim.x + threadIdx.x) >> 5;  // one warp per target
    int lane = threadIdx.x & 31;
    if (gw >= BATCH * NT) return;
    int b = gw >> 11;

    float lower = g_minmax[0];
    float dt = (g_minmax[1] - lower) / (float)(TG - 1);
    float inv_dt = 1.f / dt;
    float x = __ldg(&xt[gw]);
    float ls = __ldg(pls), osv = __ldg(pos_);
    float inv2 = 0.5f / (ls * ls);
    float R = fabsf(ls) * RFAC;

    int ilo = max(0, (int)ceilf((x - R - lower) * inv_dt));
    int ihi = min(TG - 1, (int)floorf((x + R - lower) * inv_dt));

    const float2* fv = g_f + b * TG;
    float mu = 0.f, sg = 0.f;
    for (int i = ilo + lane; i <= ihi; i += 32) {
        float2 v = __ldg(&fv[i]);
        float d = x - (lower + i * dt);
        float ev = __expf(-d * d * inv2);
        mu += ev * v.x;
        sg += ev * v.y;
    }
    #pragma unroll
    for (int off = 16; off; off >>= 1) {
        mu += __shfl_xor_sync(0xffffffffu, mu, off);
        sg += __shfl_xor_sync(0xffffffffu, sg, off);
    }
    if (lane == 0) {
        reinterpret_cast<float2*>(out)[gw] = make_float2(mu * osv, sg * osv);
    }
}

// ---------------- launch ----------------
extern "C" void kernel_launch(void* const* d_in, const int* in_sizes, int n_in,
                              void* d_out, int out_size) {
    const float* xc = (const float*)d_in[0];
    const float* yc = (const float*)d_in[1];
    const float* xt = (const float*)d_in[2];
    const float* ls_psi = (const float*)d_in[3];
    const float* os_psi = (const float*)d_in[4];
    const float* ls_rho = (const float*)d_in[5];
    const float* os_rho = (const float*)d_in[6];
    const float* w1 = (const float*)d_in[7];
    const float* b1 = (const float*)d_in[8];
    const float* w2 = (const float*)d_in[9];
    const float* b2 = (const float*)d_in[10];
    const float* w3 = (const float*)d_in[11];
    const float* b3 = (const float*)d_in[12];
    const float* w4 = (const float*)d_in[13];
    const float* b4 = (const float*)d_in[14];
    float* out = (float*)d_out;

    cudaFuncSetAttribute(conv_kernel,
                         cudaFuncAttributeMaxDynamicSharedMemorySize, SMEM_BYTES);

    sort_kernel<<<BATCH, 256>>>(xc, yc, xt);
    psi_kernel<<<(BATCH * TG) / 8, 256>>>(ls_psi, os_psi);
    conv_kernel<<<BATCH * (TG / T_TILE), CNTH, SMEM_BYTES>>>(w1, b1, w2, b2, w3, b3, w4, b4);
    rho_kernel<<<(BATCH * NT) / 8, 256>>>(xt, ls_rho, os_rho, out);
}

// round 8
// speedup vs baseline: 3.7312x; 1.1860x over previous
#include <cuda_runtime.h>
#include <math.h>

#define BATCH 16
#define NC    2048
#define NT    2048
#define TG    2048
#define NBINS 128
#define RFAC  4.0f     // truncation tail ~ erfc(4/sqrt2) = 6.6e-5 << 1e-3 gate
#define EPS   1e-8f
#define LOG2E 1.4426950408889634f

__device__ __forceinline__ float ex2(float x) {
    float y;
    asm("ex2.approx.ftz.f32 %0, %1;" : "=f"(y) : "f"(x));
    return y;
}

// Fixed binning: xc is uniform in [0, 128). Bin width = 1.0. Clamped => safe.
__device__ __forceinline__ int bin_fix(float x) {
    int b = (int)floorf(x);
    return min(NBINS - 1, max(0, b));
}

// ---------------- scratch (no allocs allowed) ----------------
__device__ float    g_minmax[2];                 // [lower, upper] (final)
__device__ float    g_plo[BATCH], g_phi[BATCH];  // per-batch partials
__device__ unsigned g_done = 0;                  // completion counter (self-resetting)
__device__ int      g_starts[BATCH * (NBINS + 1)];
__device__ float2   g_sxy[BATCH * NC];           // (xc, yc) sorted by bin
__device__ float2   g_h[BATCH * TG];             // (h0, h1)
__device__ float2   g_f[BATCH * TG];             // (f_mu, softplus(f_sigma))

// ---------------- K1: fused hist + scan + scatter + minmax ----------------
#define SPT 8   // NC / 256
__global__ __launch_bounds__(256) void sort_kernel(
    const float* __restrict__ xc, const float* __restrict__ yc,
    const float* __restrict__ xt) {
    __shared__ int scnt[NBINS];
    __shared__ int scur[NBINS];
    __shared__ int wsum[8];
    __shared__ float slo[8], shi[8];
    int b = blockIdx.x, tid = threadIdx.x;
    int lane = tid & 31, w = tid >> 5;

    for (int i = tid; i < NBINS; i += 256) scnt[i] = 0;
    __syncthreads();

    const float* xcb = xc + b * NC;
    const float* ycb = yc + b * NC;
    const float* xtb = xt + b * NT;
    float xv[SPT], yv[SPT];
    float lo = INFINITY, hi = -INFINITY;
    #pragma unroll
    for (int r = 0; r < SPT; r++) {
        int i = tid + r * 256;
        xv[r] = __ldg(&xcb[i]);
        yv[r] = __ldg(&ycb[i]);
    }
    #pragma unroll
    for (int r = 0; r < SPT; r++) {
        lo = fminf(lo, xv[r]); hi = fmaxf(hi, xv[r]);
        atomicAdd(&scnt[bin_fix(xv[r])], 1);
    }
    #pragma unroll
    for (int r = 0; r < SPT; r++) {
        float v = __ldg(&xtb[tid + r * 256]);
        lo = fminf(lo, v); hi = fmaxf(hi, v);
    }
    #pragma unroll
    for (int off = 16; off; off >>= 1) {
        lo = fminf(lo, __shfl_xor_sync(0xffffffffu, lo, off));
        hi = fmaxf(hi, __shfl_xor_sync(0xffffffffu, hi, off));
    }
    if (lane == 0) { slo[w] = lo; shi[w] = hi; }
    __syncthreads();

    // exclusive scan of the 128 bin counts (threads >= 128 carry 0)
    int c = (tid < NBINS) ? scnt[tid] : 0;
    int v = c;
    #pragma unroll
    for (int off = 1; off < 32; off <<= 1) {
        int n = __shfl_up_sync(0xffffffffu, v, off);
        if (lane >= off) v += n;
    }
    if (lane == 31) wsum[w] = v;
    __syncthreads();
    if (tid == 0) {
        int run = 0;
        #pragma unroll
        for (int k = 0; k < 8; k++) { int t = wsum[k]; wsum[k] = run; run += t; }
        float flo = slo[0], fhi = shi[0];
        #pragma unroll
        for (int k = 1; k < 8; k++) { flo = fminf(flo, slo[k]); fhi = fmaxf(fhi, shi[k]); }
        g_plo[b] = flo; g_phi[b] = fhi;
    }
    __syncthreads();
    if (tid < NBINS) {
        int excl = v - c + wsum[w];
        scur[tid] = excl;
        g_starts[b * (NBINS + 1) + tid] = excl;
    }
    if (tid == 0) g_starts[b * (NBINS + 1) + NBINS] = NC;
    __syncthreads();

    // scatter from registers via smem cursors
    #pragma unroll
    for (int r = 0; r < SPT; r++) {
        int pos = atomicAdd(&scur[bin_fix(xv[r])], 1);
        g_sxy[b * NC + pos] = make_float2(xv[r], yv[r]);
    }

    // last block folds per-batch min/max partials into g_minmax
    __threadfence();
    if (tid == 0) {
        if (atomicAdd(&g_done, 1) == BATCH - 1) {
            __threadfence();
            volatile float* plo = g_plo;
            volatile float* phi = g_phi;
            float flo = INFINITY, fhi = -INFINITY;
            #pragma unroll
            for (int k = 0; k < BATCH; k++) {
                flo = fminf(flo, plo[k]); fhi = fmaxf(fhi, phi[k]);
            }
            g_minmax[0] = flo; g_minmax[1] = fhi;
            g_done = 0;
            __threadfence();
        }
    }
}

// ---------------- K2: psi stage — 8 lanes per t-point ----------------
__global__ void psi_kernel(const float* __restrict__ pls,
                           const float* __restrict__ pos_) {
    int g = (blockIdx.x * blockDim.x + threadIdx.x) >> 3;   // group id = t-point
    int sub = threadIdx.x & 7;
    if (g >= BATCH * TG) return;
    int b = g >> 11, i = g & (TG - 1);

    float lower = g_minmax[0], upper = g_minmax[1];
    float dt = (upper - lower) / (float)(TG - 1);
    float t = lower + i * dt;
    float ls = __ldg(pls), osv = __ldg(pos_);
    float nc2 = -0.5f * LOG2E / (ls * ls);   // exponent coefficient (base-2)
    float R = fabsf(ls) * RFAC;

    int blo = min(NBINS - 1, max(0, (int)floorf(t - R)));
    int bhi = min(NBINS - 1, max(0, (int)floorf(t + R)));
    int s = g_starts[b * (NBINS + 1) + blo];
    int e = g_starts[b * (NBINS + 1) + bhi + 1];

    const float2* sxy = g_sxy + b * NC;
    float a0 = 0.f, a1 = 0.f;
    for (int k = s + sub; k < e; k += 8) {
        float2 xy = __ldg(&sxy[k]);
        float d = t - xy.x;
        float ev = ex2(d * d * nc2);
        a0 += ev;
        a1 += ev * xy.y;
    }
    #pragma unroll
    for (int off = 4; off; off >>= 1) {
        a0 += __shfl_xor_sync(0xffffffffu, a0, off);
        a1 += __shfl_xor_sync(0xffffffffu, a1, off);
    }
    if (sub == 0) {
        a0 *= osv; a1 *= osv;
        g_h[g] = make_float2(a0, a1 / (a0 + EPS));
    }
}

// ---------------- K3: fused 4-layer conv chain (P=4 x Q=4 register-blocked) ----------------
#define T_TILE 128
#define HALO   8
#define CW     (T_TILE + 2 * HALO)  // 144
#define CWP    152                  // padded row stride (floats), mult of 4
#define CNTH   256

// dynamic smem layout (floats), all offsets multiples of 4 (16B aligned)
#define OFF_S0  0
#define OFF_S1  (OFF_S0 + 3 * CWP)     // 456
#define OFF_S2  (OFF_S1 + 16 * CWP)    // 2888
#define OFF_W1  (OFF_S2 + 32 * CWP)    // 7752
#define OFF_W2  (OFF_W1 + 240)         // 7992
#define OFF_W3  (OFF_W2 + 2560)        // 10552
#define OFF_W4  (OFF_W3 + 2560)        // 13112
#define OFF_B1  (OFF_W4 + 160)         // 13272
#define OFF_B2  (OFF_B1 + 16)
#define OFF_B3  (OFF_B2 + 32)
#define OFF_B4  (OFF_B3 + 16)
#define SMEM_FLOATS (OFF_B4 + 4)
#define SMEM_BYTES  (SMEM_FLOATS * 4)

template <int NCO, int NCI, int LO>
__device__ __forceinline__ void conv_layer(const float* __restrict__ sin,
                                           float* __restrict__ sout,
                                           const float4* __restrict__ sw4,
                                           const float* __restrict__ sb,
                                           int p0, int tid) {
    constexpr int nv = CW - 2 * LO;         // 140 / 136 / 132 (all % 4 == 0)
    constexpr int ngp = nv / 4;
    constexpr int ncog = NCO / 4;
    constexpr int off = (LO - 2) & 3;       // 0 / 2 / 0

    for (int task = tid; task < ncog * ngp; task += CNTH) {
        int gp = task % ngp;
        int cog = task / ngp;
        int u0 = LO + gp * 4;
        int base = u0 - 2 - off;            // 16B aligned, >= 0

        float acc[4][4];
        #pragma unroll
        for (int q = 0; q < 4; q++)
            #pragma unroll
            for (int j = 0; j < 4; j++) acc[q][j] = 0.f;

        for (int ci = 0; ci < NCI; ci++) {
            const float4* sr = reinterpret_cast<const float4*>(sin + ci * CWP + base);
            float4 A = sr[0], B = sr[1], C = sr[2];
            float win[12] = {A.x, A.y, A.z, A.w, B.x, B.y, B.z, B.w,
                             C.x, C.y, C.z, C.w};
            #pragma unroll
            for (int k = 0; k < 5; k++) {
                float4 wv = sw4[(cog * NCI + ci) * 5 + k];
                #pragma unroll
                for (int j = 0; j < 4; j++) {
                    float xv = win[off + k + j];
                    acc[0][j] = fmaf(wv.x, xv, acc[0][j]);
                    acc[1][j] = fmaf(wv.y, xv, acc[1][j]);
                    acc[2][j] = fmaf(wv.z, xv, acc[2][j]);
                    acc[3][j] = fmaf(wv.w, xv, acc[3][j]);
                }
            }
        }
        #pragma unroll
        for (int q = 0; q < 4; q++) {
            int co = cog * 4 + q;
            float bias = sb[co];
            float v[4];
            #pragma unroll
            for (int j = 0; j < 4; j++) {
                int p = p0 + u0 + j;
                v[j] = (p >= 0 && p < TG) ? fmaxf(acc[q][j] + bias, 0.f) : 0.f;
            }
            float2* so = reinterpret_cast<float2*>(sout + co * CWP + u0);
            so[0] = make_float2(v[0], v[1]);
            so[1] = make_float2(v[2], v[3]);
        }
    }
}

__global__ __launch_bounds__(CNTH) void conv_kernel(
    const float* __restrict__ w1, const float* __restrict__ b1,
    const float* __restrict__ w2, const float* __restrict__ b2,
    const float* __restrict__ w3, const float* __restrict__ b3,
    const float* __restrict__ w4, const float* __restrict__ b4) {
    extern __shared__ float dsm[];
    float* s0 = dsm + OFF_S0;
    float* s1 = dsm + OFF_S1;
    float* s2 = dsm + OFF_S2;

    const int tiles = TG / T_TILE;  // 16
    int b = blockIdx.x / tiles;
    int tile = blockIdx.x % tiles;
    int p0 = tile * T_TILE - HALO;
    int tid = threadIdx.x;

    // stage weights, re-packed to [cog][ci][k][coq] so a thread's 4 co-weights
    // are a single broadcast LDS.128
    for (int i = tid; i < 240; i += CNTH) {   // w1: NCI=3 -> per-cog 60
        int co = i / 15, r = i % 15;
        dsm[OFF_W1 + (co >> 2) * 60 + r * 4 + (co & 3)] = __ldg(&w1[i]);
    }
    for (int i = tid; i < 2560; i += CNTH) {  // w2: NCI=16 -> per-cog 320
        int co = i / 80, r = i % 80;
        dsm[OFF_W2 + (co >> 2) * 320 + r * 4 + (co & 3)] = __ldg(&w2[i]);
    }
    for (int i = tid; i < 2560; i += CNTH) {  // w3: NCI=32 -> per-cog 640
        int co = i / 160, r = i % 160;
        dsm[OFF_W3 + (co >> 2) * 640 + r * 4 + (co & 3)] = __ldg(&w3[i]);
    }
    for (int i = tid; i < 160; i += CNTH)  dsm[OFF_W4 + i] = __ldg(&w4[i]);  // plain
    if (tid < 16) dsm[OFF_B1 + tid] = __ldg(&b1[tid]);
    if (tid < 32) dsm[OFF_B2 + tid] = __ldg(&b2[tid]);
    if (tid >= 32 && tid < 48) dsm[OFF_B3 + tid - 32] = __ldg(&b3[tid - 32]);
    if (tid >= 48 && tid < 50) dsm[OFF_B4 + tid - 48] = __ldg(&b4[tid - 48]);

    float lower = g_minmax[0];
    float dt = (g_minmax[1] - lower) / (float)(TG - 1);

    // load input channels (t, h0, h1); zero outside [0, TG)
    for (int u = tid; u < CW; u += CNTH) {
        int p = p0 + u;
        bool in = (p >= 0 && p < TG);
        float2 h = in ? g_h[b * TG + p] : make_float2(0.f, 0.f);
        s0[0 * CWP + u] = in ? (lower + p * dt) : 0.f;
        s0[1 * CWP + u] = h.x;
        s0[2 * CWP + u] = h.y;
    }
    __syncthreads();

    conv_layer<16, 3, 2>(s0, s1, reinterpret_cast<const float4*>(dsm + OFF_W1),
                         dsm + OFF_B1, p0, tid);
    __syncthreads();
    conv_layer<32, 16, 4>(s1, s2, reinterpret_cast<const float4*>(dsm + OFF_W2),
                          dsm + OFF_B2, p0, tid);
    __syncthreads();
    conv_layer<16, 32, 6>(s2, s1, reinterpret_cast<const float4*>(dsm + OFF_W3),
                          dsm + OFF_B3, p0, tid);
    __syncthreads();

    // layer 4: 16 -> 2; one thread per position computes BOTH channels,
    // enabling a single float2 store (and float2 loads in rho).
    if (tid < T_TILE) {
        const float* sw4 = dsm + OFF_W4;
        const float* sb4 = dsm + OFF_B4;
        int u = HALO + tid;
        float acc0 = sb4[0], acc1 = sb4[1];
        #pragma unroll
        for (int ci = 0; ci < 16; ci++) {
            #pragma unroll
            for (int k = 0; k < 5; k++) {
                float xv = s1[ci * CWP + u - 2 + k];
                acc0 = fmaf(sw4[(0 * 16 + ci) * 5 + k], xv, acc0);
                acc1 = fmaf(sw4[(1 * 16 + ci) * 5 + k], xv, acc1);
            }
        }
        int p = p0 + u;                 // always in [0, TG)
        float sp = fmaxf(acc1, 0.f) + log1pf(__expf(-fabsf(acc1)));
        g_f[b * TG + p] = make_float2(acc0, sp);
    }
}

// ---------------- K4: rho stage — 8 lanes per target ----------------
__global__ void rho_kernel(const float* __restrict__ xt,
                           const float* __restrict__ pls,
                           const float* __restrict__ pos_,
                           float* __restrict__ out) {
    int g = (blockIdx.x * blockDim.x + threadIdx.x) >> 3;   // group id = target
    int sub = threadIdx.x & 7;
    if (g >= BATCH * NT) return;
    int b = g >> 11;

    float lower = g_minmax[0];
    float dt = (g_minmax[1] - lower) / (float)(TG - 1);
    float inv_dt = 1.f / dt;
    float x = __ldg(&xt[g]);
    float ls = __ldg(pls), osv = __ldg(pos_);
    float nc2 = -0.5f * LOG2E / (ls * ls);
    float R = fabsf(ls) * RFAC;

    int ilo = max(0, (int)ceilf((x - R - lower) * inv_dt));
    int ihi = min(TG - 1, (int)floorf((x + R - lower) * inv_dt));

    const float2* fv = g_f + b * TG;
    float mu = 0.f, sg = 0.f;
    float d = x - (lower + (ilo + sub) * dt);
    float dstep = 8.f * dt;
    for (int i = ilo + sub; i <= ihi; i += 8) {
        float2 v = __ldg(&fv[i]);
        float ev = ex2(d * d * nc2);
        mu = fmaf(ev, v.x, mu);
        sg = fmaf(ev, v.y, sg);
        d -= dstep;
    }
    #pragma unroll
    for (int off = 4; off; off >>= 1) {
        mu += __shfl_xor_sync(0xffffffffu, mu, off);
        sg += __shfl_xor_sync(0xffffffffu, sg, off);
    }
    if (sub == 0) {
        reinterpret_cast<float2*>(out)[g] = make_float2(mu * osv, sg * osv);
    }
}

// ---------------- launch ----------------
extern "C" void kernel_launch(void* const* d_in, const int* in_sizes, int n_in,
                              void* d_out, int out_size) {
    const float* xc = (const float*)d_in[0];
    const float* yc = (const float*)d_in[1];
    const float* xt = (const float*)d_in[2];
    const float* ls_psi = (const float*)d_in[3];
    const float* os_psi = (const float*)d_in[4];
    const float* ls_rho = (const float*)d_in[5];
    const float* os_rho = (const float*)d_in[6];
    const float* w1 = (const float*)d_in[7];
    const float* b1 = (const float*)d_in[8];
    const float* w2 = (const float*)d_in[9];
    const float* b2 = (const float*)d_in[10];
    const float* w3 = (const float*)d_in[11];
    const float* b3 = (const float*)d_in[12];
    const float* w4 = (const float*)d_in[13];
    const float* b4 = (const float*)d_in[14];
    float* out = (float*)d_out;

    cudaFuncSetAttribute(conv_kernel,
                         cudaFuncAttributeMaxDynamicSharedMemorySize, SMEM_BYTES);

    sort_kernel<<<BATCH, 256>>>(xc, yc, xt);
    psi_kernel<<<(BATCH * TG) * 8 / 256, 256>>>(ls_psi, os_psi);
    conv_kernel<<<BATCH * (TG / T_TILE), CNTH, SMEM_BYTES>>>(w1, b1, w2, b2, w3, b3, w4, b4);
    rho_kernel<<<(BATCH * NT) * 8 / 256, 256>>>(xt, ls_rho, os_rho, out);
}

// round 9
// speedup vs baseline: 3.7472x; 1.0043x over previous
#include <cuda_runtime.h>
#include <math.h>

#define BATCH 16
#define NC    2048
#define NT    2048
#define TG    2048
#define NBINS 128
#define RFAC  3.75f    // truncation tail ~ erfc(3.75/sqrt2) = 1.8e-4 << 1e-3 gate
#define EPS   1e-8f
#define LOG2E 1.4426950408889634f

__device__ __forceinline__ float ex2(float x) {
    float y;
    asm("ex2.approx.ftz.f32 %0, %1;" : "=f"(y) : "f"(x));
    return y;
}

// Fixed binning: xc is uniform in [0, 128). Bin width = 1.0. Clamped => safe.
__device__ __forceinline__ int bin_fix(float x) {
    int b = (int)floorf(x);
    return min(NBINS - 1, max(0, b));
}

// ---------------- scratch (no allocs allowed) ----------------
__device__ float    g_minmax[2];                 // [lower, upper] (final)
__device__ float    g_plo[BATCH], g_phi[BATCH];  // per-batch partials
__device__ unsigned g_done = 0;                  // completion counter (self-resetting)
__device__ int      g_starts[BATCH * (NBINS + 1)];
__device__ float2   g_sxy[BATCH * NC];           // (xc, yc) sorted by bin
__device__ float2   g_h[BATCH * TG];             // (h0, h1)
__device__ float2   g_f[BATCH * TG];             // (f_mu, softplus(f_sigma))

// ---------------- K1: fused hist + scan + scatter + minmax ----------------
#define SNTH 512
#define SPT  4   // NC / SNTH
__global__ __launch_bounds__(SNTH) void sort_kernel(
    const float* __restrict__ xc, const float* __restrict__ yc,
    const float* __restrict__ xt) {
    __shared__ int scnt[NBINS];
    __shared__ int scur[NBINS];
    __shared__ int wsum[16];
    __shared__ float slo[16], shi[16];
    int b = blockIdx.x, tid = threadIdx.x;
    int lane = tid & 31, w = tid >> 5;

    for (int i = tid; i < NBINS; i += SNTH) scnt[i] = 0;
    __syncthreads();

    const float* xcb = xc + b * NC;
    const float* ycb = yc + b * NC;
    const float* xtb = xt + b * NT;
    float xv[SPT], yv[SPT];
    float lo = INFINITY, hi = -INFINITY;
    #pragma unroll
    for (int r = 0; r < SPT; r++) {
        int i = tid + r * SNTH;
        xv[r] = __ldg(&xcb[i]);
        yv[r] = __ldg(&ycb[i]);
    }
    #pragma unroll
    for (int r = 0; r < SPT; r++) {
        lo = fminf(lo, xv[r]); hi = fmaxf(hi, xv[r]);
        atomicAdd(&scnt[bin_fix(xv[r])], 1);
    }
    #pragma unroll
    for (int r = 0; r < SPT; r++) {
        float v = __ldg(&xtb[tid + r * SNTH]);
        lo = fminf(lo, v); hi = fmaxf(hi, v);
    }
    #pragma unroll
    for (int off = 16; off; off >>= 1) {
        lo = fminf(lo, __shfl_xor_sync(0xffffffffu, lo, off));
        hi = fmaxf(hi, __shfl_xor_sync(0xffffffffu, hi, off));
    }
    if (lane == 0) { slo[w] = lo; shi[w] = hi; }
    __syncthreads();

    // exclusive scan of the 128 bin counts (threads >= 128 carry 0)
    int c = (tid < NBINS) ? scnt[tid] : 0;
    int v = c;
    #pragma unroll
    for (int off = 1; off < 32; off <<= 1) {
        int n = __shfl_up_sync(0xffffffffu, v, off);
        if (lane >= off) v += n;
    }
    if (lane == 31) wsum[w] = v;
    __syncthreads();
    if (tid == 0) {
        int run = 0;
        #pragma unroll
        for (int k = 0; k < 16; k++) { int t = wsum[k]; wsum[k] = run; run += t; }
        float flo = slo[0], fhi = shi[0];
        #pragma unroll
        for (int k = 1; k < 16; k++) { flo = fminf(flo, slo[k]); fhi = fmaxf(fhi, shi[k]); }
        g_plo[b] = flo; g_phi[b] = fhi;
    }
    __syncthreads();
    if (tid < NBINS) {
        int excl = v - c + wsum[w];
        scur[tid] = excl;
        g_starts[b * (NBINS + 1) + tid] = excl;
    }
    if (tid == 0) g_starts[b * (NBINS + 1) + NBINS] = NC;
    __syncthreads();

    // scatter from registers via smem cursors
    #pragma unroll
    for (int r = 0; r < SPT; r++) {
        int pos = atomicAdd(&scur[bin_fix(xv[r])], 1);
        g_sxy[b * NC + pos] = make_float2(xv[r], yv[r]);
    }

    // last block folds per-batch min/max partials into g_minmax
    __threadfence();
    if (tid == 0) {
        if (atomicAdd(&g_done, 1) == BATCH - 1) {
            __threadfence();
            volatile float* plo = g_plo;
            volatile float* phi = g_phi;
            float flo = INFINITY, fhi = -INFINITY;
            #pragma unroll
            for (int k = 0; k < BATCH; k++) {
                flo = fminf(flo, plo[k]); fhi = fmaxf(fhi, phi[k]);
            }
            g_minmax[0] = flo; g_minmax[1] = fhi;
            g_done = 0;
            __threadfence();
        }
    }
}

// ---------------- K2: psi stage — 8 lanes per t-point, x2 unrolled ----------------
__global__ void psi_kernel(const float* __restrict__ pls,
                           const float* __restrict__ pos_) {
    int g = (blockIdx.x * blockDim.x + threadIdx.x) >> 3;   // group id = t-point
    int sub = threadIdx.x & 7;
    if (g >= BATCH * TG) return;
    int b = g >> 11, i = g & (TG - 1);

    float lower = g_minmax[0], upper = g_minmax[1];
    float dt = (upper - lower) / (float)(TG - 1);
    float t = lower + i * dt;
    float ls = __ldg(pls), osv = __ldg(pos_);
    float nc2 = -0.5f * LOG2E / (ls * ls);   // exponent coefficient (base-2)
    float R = fabsf(ls) * RFAC;

    int blo = min(NBINS - 1, max(0, (int)floorf(t - R)));
    int bhi = min(NBINS - 1, max(0, (int)floorf(t + R)));
    int s = g_starts[b * (NBINS + 1) + blo];
    int e = g_starts[b * (NBINS + 1) + bhi + 1];

    const float2* sxy = g_sxy + b * NC;
    float a00 = 0.f, a10 = 0.f, a01 = 0.f, a11 = 0.f;
    int k = s + sub;
    for (; k + 8 < e; k += 16) {                 // two independent chains
        float2 p0 = __ldg(&sxy[k]);
        float2 p1 = __ldg(&sxy[k + 8]);
        float d0 = t - p0.x;
        float d1 = t - p1.x;
        float e0 = ex2(d0 * d0 * nc2);
        float e1 = ex2(d1 * d1 * nc2);
        a00 += e0; a10 = fmaf(e0, p0.y, a10);
        a01 += e1; a11 = fmaf(e1, p1.y, a11);
    }
    if (k < e) {                                 // at most one leftover
        float2 p0 = __ldg(&sxy[k]);
        float d0 = t - p0.x;
        float e0 = ex2(d0 * d0 * nc2);
        a00 += e0; a10 = fmaf(e0, p0.y, a10);
    }
    float a0 = a00 + a01, a1 = a10 + a11;
    #pragma unroll
    for (int off = 4; off; off >>= 1) {
        a0 += __shfl_xor_sync(0xffffffffu, a0, off);
        a1 += __shfl_xor_sync(0xffffffffu, a1, off);
    }
    if (sub == 0) {
        a0 *= osv; a1 *= osv;
        g_h[g] = make_float2(a0, a1 / (a0 + EPS));
    }
}

// ---------------- K3: fused 4-layer conv chain (P=4 x Q=4 register-blocked) ----------------
#define T_TILE 128
#define HALO   8
#define CW     (T_TILE + 2 * HALO)  // 144
#define CWP    152                  // padded row stride (floats), mult of 4
#define CNTH   256

// dynamic smem layout (floats), all offsets multiples of 4 (16B aligned)
#define OFF_S0  0
#define OFF_S1  (OFF_S0 + 3 * CWP)     // 456
#define OFF_S2  (OFF_S1 + 16 * CWP)    // 2888
#define OFF_W1  (OFF_S2 + 32 * CWP)    // 7752
#define OFF_W2  (OFF_W1 + 240)         // 7992
#define OFF_W3  (OFF_W2 + 2560)        // 10552
#define OFF_W4  (OFF_W3 + 2560)        // 13112
#define OFF_B1  (OFF_W4 + 160)         // 13272
#define OFF_B2  (OFF_B1 + 16)
#define OFF_B3  (OFF_B2 + 32)
#define OFF_B4  (OFF_B3 + 16)
#define SMEM_FLOATS (OFF_B4 + 4)
#define SMEM_BYTES  (SMEM_FLOATS * 4)

template <int NCO, int NCI, int LO>
__device__ __forceinline__ void conv_layer(const float* __restrict__ sin,
                                           float* __restrict__ sout,
                                           const float4* __restrict__ sw4,
                                           const float* __restrict__ sb,
                                           int p0, int tid) {
    constexpr int nv = CW - 2 * LO;         // 140 / 136 / 132 (all % 4 == 0)
    constexpr int ngp = nv / 4;
    constexpr int ncog = NCO / 4;
    constexpr int off = (LO - 2) & 3;       // 0 / 2 / 0

    for (int task = tid; task < ncog * ngp; task += CNTH) {
        int gp = task % ngp;
        int cog = task / ngp;
        int u0 = LO + gp * 4;
        int base = u0 - 2 - off;            // 16B aligned, >= 0

        float acc[4][4];
        #pragma unroll
        for (int q = 0; q < 4; q++)
            #pragma unroll
            for (int j = 0; j < 4; j++) acc[q][j] = 0.f;

        for (int ci = 0; ci < NCI; ci++) {
            const float4* sr = reinterpret_cast<const float4*>(sin + ci * CWP + base);
            float4 A = sr[0], B = sr[1], C = sr[2];
            float win[12] = {A.x, A.y, A.z, A.w, B.x, B.y, B.z, B.w,
                             C.x, C.y, C.z, C.w};
            #pragma unroll
            for (int k = 0; k < 5; k++) {
                float4 wv = sw4[(cog * NCI + ci) * 5 + k];
                #pragma unroll
                for (int j = 0; j < 4; j++) {
                    float xv = win[off + k + j];
                    acc[0][j] = fmaf(wv.x, xv, acc[0][j]);
                    acc[1][j] = fmaf(wv.y, xv, acc[1][j]);
                    acc[2][j] = fmaf(wv.z, xv, acc[2][j]);
                    acc[3][j] = fmaf(wv.w, xv, acc[3][j]);
                }
            }
        }
        #pragma unroll
        for (int q = 0; q < 4; q++) {
            int co = cog * 4 + q;
            float bias = sb[co];
            float v[4];
            #pragma unroll
            for (int j = 0; j < 4; j++) {
                int p = p0 + u0 + j;
                v[j] = (p >= 0 && p < TG) ? fmaxf(acc[q][j] + bias, 0.f) : 0.f;
            }
            float2* so = reinterpret_cast<float2*>(sout + co * CWP + u0);
            so[0] = make_float2(v[0], v[1]);
            so[1] = make_float2(v[2], v[3]);
        }
    }
}

__global__ __launch_bounds__(CNTH) void conv_kernel(
    const float* __restrict__ w1, const float* __restrict__ b1,
    const float* __restrict__ w2, const float* __restrict__ b2,
    const float* __restrict__ w3, const float* __restrict__ b3,
    const float* __restrict__ w4, const float* __restrict__ b4) {
    extern __shared__ float dsm[];
    float* s0 = dsm + OFF_S0;
    float* s1 = dsm + OFF_S1;
    float* s2 = dsm + OFF_S2;

    const int tiles = TG / T_TILE;  // 16
    int b = blockIdx.x / tiles;
    int tile = blockIdx.x % tiles;
    int p0 = tile * T_TILE - HALO;
    int tid = threadIdx.x;

    // stage weights, re-packed to [cog][ci][k][coq] so a thread's 4 co-weights
    // are a single broadcast LDS.128
    for (int i = tid; i < 240; i += CNTH) {   // w1: NCI=3 -> per-cog 60
        int co = i / 15, r = i % 15;
        dsm[OFF_W1 + (co >> 2) * 60 + r * 4 + (co & 3)] = __ldg(&w1[i]);
    }
    for (int i = tid; i < 2560; i += CNTH) {  // w2: NCI=16 -> per-cog 320
        int co = i / 80, r = i % 80;
        dsm[OFF_W2 + (co >> 2) * 320 + r * 4 + (co & 3)] = __ldg(&w2[i]);
    }
    for (int i = tid; i < 2560; i += CNTH) {  // w3: NCI=32 -> per-cog 640
        int co = i / 160, r = i % 160;
        dsm[OFF_W3 + (co >> 2) * 640 + r * 4 + (co & 3)] = __ldg(&w3[i]);
    }
    for (int i = tid; i < 160; i += CNTH)  dsm[OFF_W4 + i] = __ldg(&w4[i]);  // plain
    if (tid < 16) dsm[OFF_B1 + tid] = __ldg(&b1[tid]);
    if (tid < 32) dsm[OFF_B2 + tid] = __ldg(&b2[tid]);
    if (tid >= 32 && tid < 48) dsm[OFF_B3 + tid - 32] = __ldg(&b3[tid - 32]);
    if (tid >= 48 && tid < 50) dsm[OFF_B4 + tid - 48] = __ldg(&b4[tid - 48]);

    float lower = g_minmax[0];
    float dt = (g_minmax[1] - lower) / (float)(TG - 1);

    // load input channels (t, h0, h1); zero outside [0, TG)
    for (int u = tid; u < CW; u += CNTH) {
        int p = p0 + u;
        bool in = (p >= 0 && p < TG);
        float2 h = in ? g_h[b * TG + p] : make_float2(0.f, 0.f);
        s0[0 * CWP + u] = in ? (lower + p * dt) : 0.f;
        s0[1 * CWP + u] = h.x;
        s0[2 * CWP + u] = h.y;
    }
    __syncthreads();

    conv_layer<16, 3, 2>(s0, s1, reinterpret_cast<const float4*>(dsm + OFF_W1),
                         dsm + OFF_B1, p0, tid);
    __syncthreads();
    conv_layer<32, 16, 4>(s1, s2, reinterpret_cast<const float4*>(dsm + OFF_W2),
                          dsm + OFF_B2, p0, tid);
    __syncthreads();
    conv_layer<16, 32, 6>(s2, s1, reinterpret_cast<const float4*>(dsm + OFF_W3),
                          dsm + OFF_B3, p0, tid);
    __syncthreads();

    // layer 4: 16 -> 2; one thread per position computes BOTH channels,
    // enabling a single float2 store (and float2 loads in rho).
    if (tid < T_TILE) {
        const float* sw4 = dsm + OFF_W4;
        const float* sb4 = dsm + OFF_B4;
        int u = HALO + tid;
        float acc0 = sb4[0], acc1 = sb4[1];
        #pragma unroll
        for (int ci = 0; ci < 16; ci++) {
            #pragma unroll
            for (int k = 0; k < 5; k++) {
                float xv = s1[ci * CWP + u - 2 + k];
                acc0 = fmaf(sw4[(0 * 16 + ci) * 5 + k], xv, acc0);
                acc1 = fmaf(sw4[(1 * 16 + ci) * 5 + k], xv, acc1);
            }
        }
        int p = p0 + u;                 // always in [0, TG)
        float sp = fmaxf(acc1, 0.f) + log1pf(__expf(-fabsf(acc1)));
        g_f[b * TG + p] = make_float2(acc0, sp);
    }
}

// ---------------- K4: rho stage — 8 lanes per target, x2 unrolled ----------------
__global__ void rho_kernel(const float* __restrict__ xt,
                           const float* __restrict__ pls,
                           const float* __restrict__ pos_,
                           float* __restrict__ out) {
    int g = (blockIdx.x * blockDim.x + threadIdx.x) >> 3;   // group id = target
    int sub = threadIdx.x & 7;
    if (g >= BATCH * NT) return;
    int b = g >> 11;

    float lower = g_minmax[0];
    float dt = (g_minmax[1] - lower) / (float)(TG - 1);
    float inv_dt = 1.f / dt;
    float x = __ldg(&xt[g]);
    float ls = __ldg(pls), osv = __ldg(pos_);
    float nc2 = -0.5f * LOG2E / (ls * ls);
    float R = fabsf(ls) * RFAC;

    int ilo = max(0, (int)ceilf((x - R - lower) * inv_dt));
    int ihi = min(TG - 1, (int)floorf((x + R - lower) * inv_dt));

    const float2* fv = g_f + b * TG;
    float mu0 = 0.f, sg0 = 0.f, mu1 = 0.f, sg1 = 0.f;
    int i = ilo + sub;
    float d0 = x - (lower + i * dt);
    float d1 = d0 - 8.f * dt;
    float step16 = 16.f * dt;
    for (; i + 8 <= ihi; i += 16) {              // two independent chains
        float2 v0 = __ldg(&fv[i]);
        float2 v1 = __ldg(&fv[i + 8]);
        float e0 = ex2(d0 * d0 * nc2);
        float e1 = ex2(d1 * d1 * nc2);
        mu0 = fmaf(e0, v0.x, mu0); sg0 = fmaf(e0, v0.y, sg0);
        mu1 = fmaf(e1, v1.x, mu1); sg1 = fmaf(e1, v1.y, sg1);
        d0 -= step16; d1 -= step16;
    }
    if (i <= ihi) {                              // at most one leftover
        float2 v0 = __ldg(&fv[i]);
        float e0 = ex2(d0 * d0 * nc2);
        mu0 = fmaf(e0, v0.x, mu0); sg0 = fmaf(e0, v0.y, sg0);
    }
    float mu = mu0 + mu1, sg = sg0 + sg1;
    #pragma unroll
    for (int off = 4; off; off >>= 1) {
        mu += __shfl_xor_sync(0xffffffffu, mu, off);
        sg += __shfl_xor_sync(0xffffffffu, sg, off);
    }
    if (sub == 0) {
        reinterpret_cast<float2*>(out)[g] = make_float2(mu * osv, sg * osv);
    }
}

// ---------------- launch ----------------
extern "C" void kernel_launch(void* const* d_in, const int* in_sizes, int n_in,
                              void* d_out, int out_size) {
    const float* xc = (const float*)d_in[0];
    const float* yc = (const float*)d_in[1];
    const float* xt = (const float*)d_in[2];
    const float* ls_psi = (const float*)d_in[3];
    const float* os_psi = (const float*)d_in[4];
    const float* ls_rho = (const float*)d_in[5];
    const float* os_rho = (const float*)d_in[6];
    const float* w1 = (const float*)d_in[7];
    const float* b1 = (const float*)d_in[8];
    const float* w2 = (const float*)d_in[9];
    const float* b2 = (const float*)d_in[10];
    const float* w3 = (const float*)d_in[11];
    const float* b3 = (const float*)d_in[12];
    const float* w4 = (const float*)d_in[13];
    const float* b4 = (const float*)d_in[14];
    float* out = (float*)d_out;

    cudaFuncSetAttribute(conv_kernel,
                         cudaFuncAttributeMaxDynamicSharedMemorySize, SMEM_BYTES);

    sort_kernel<<<BATCH, SNTH>>>(xc, yc, xt);
    psi_kernel<<<(BATCH * TG) * 8 / 256, 256>>>(ls_psi, os_psi);
    conv_kernel<<<BATCH * (TG / T_TILE), CNTH, SMEM_BYTES>>>(w1, b1, w2, b2, w3, b3, w4, b4);
    rho_kernel<<<(BATCH * NT) * 8 / 256, 256>>>(xt, ls_rho, os_rho, out);
}

// round 10
// speedup vs baseline: 3.9326x; 1.0495x over previous
#include <cuda_runtime.h>
#include <math.h>

#define BATCH 16
#define NC    2048
#define NT    2048
#define TG    2048
#define NBINS 128
#define RFAC  3.75f    // truncation tail ~ erfc(3.75/sqrt2) = 1.8e-4 << 1e-3 gate
#define EPS   1e-8f
#define LOG2E 1.4426950408889634f

__device__ __forceinline__ float ex2(float x) {
    float y;
    asm("ex2.approx.ftz.f32 %0, %1;" : "=f"(y) : "f"(x));
    return y;
}

// Fixed binning: xc is uniform in [0, 128). Bin width = 1.0. Clamped => safe.
__device__ __forceinline__ int bin_fix(float x) {
    int b = (int)floorf(x);
    return min(NBINS - 1, max(0, b));
}

// ---------------- scratch (no allocs allowed) ----------------
__device__ float    g_minmax[2];                 // [lower, upper] (final)
__device__ float    g_plo[BATCH], g_phi[BATCH];  // per-batch partials
__device__ unsigned g_done = 0;                  // completion counter (self-resetting)
__device__ int      g_starts[BATCH * (NBINS + 1)];
__device__ __align__(16) float2 g_sxy[BATCH * NC];  // (xc, yc) sorted by bin
__device__ __align__(16) float2 g_h[BATCH * TG];    // (h0, h1)
__device__ __align__(16) float2 g_f[BATCH * TG];    // (f_mu, softplus(f_sigma))

// ---------------- K1: fused hist + scan + scatter + minmax ----------------
#define SNTH 512
#define SPT  4   // NC / SNTH
__global__ __launch_bounds__(SNTH) void sort_kernel(
    const float* __restrict__ xc, const float* __restrict__ yc,
    const float* __restrict__ xt) {
    __shared__ int scnt[NBINS];
    __shared__ int scur[NBINS];
    __shared__ int wsum[16];
    __shared__ float slo[16], shi[16];
    int b = blockIdx.x, tid = threadIdx.x;
    int lane = tid & 31, w = tid >> 5;

    for (int i = tid; i < NBINS; i += SNTH) scnt[i] = 0;
    __syncthreads();

    const float* xcb = xc + b * NC;
    const float* ycb = yc + b * NC;
    const float* xtb = xt + b * NT;
    float xv[SPT], yv[SPT];
    float lo = INFINITY, hi = -INFINITY;
    #pragma unroll
    for (int r = 0; r < SPT; r++) {
        int i = tid + r * SNTH;
        xv[r] = __ldg(&xcb[i]);
        yv[r] = __ldg(&ycb[i]);
    }
    #pragma unroll
    for (int r = 0; r < SPT; r++) {
        lo = fminf(lo, xv[r]); hi = fmaxf(hi, xv[r]);
        atomicAdd(&scnt[bin_fix(xv[r])], 1);
    }
    #pragma unroll
    for (int r = 0; r < SPT; r++) {
        float v = __ldg(&xtb[tid + r * SNTH]);
        lo = fminf(lo, v); hi = fmaxf(hi, v);
    }
    #pragma unroll
    for (int off = 16; off; off >>= 1) {
        lo = fminf(lo, __shfl_xor_sync(0xffffffffu, lo, off));
        hi = fmaxf(hi, __shfl_xor_sync(0xffffffffu, hi, off));
    }
    if (lane == 0) { slo[w] = lo; shi[w] = hi; }
    __syncthreads();

    // exclusive scan of the 128 bin counts (threads >= 128 carry 0)
    int c = (tid < NBINS) ? scnt[tid] : 0;
    int v = c;
    #pragma unroll
    for (int off = 1; off < 32; off <<= 1) {
        int n = __shfl_up_sync(0xffffffffu, v, off);
        if (lane >= off) v += n;
    }
    if (lane == 31) wsum[w] = v;
    __syncthreads();
    if (tid == 0) {
        int run = 0;
        #pragma unroll
        for (int k = 0; k < 16; k++) { int t = wsum[k]; wsum[k] = run; run += t; }
        float flo = slo[0], fhi = shi[0];
        #pragma unroll
        for (int k = 1; k < 16; k++) { flo = fminf(flo, slo[k]); fhi = fmaxf(fhi, shi[k]); }
        g_plo[b] = flo; g_phi[b] = fhi;
    }
    __syncthreads();
    if (tid < NBINS) {
        int excl = v - c + wsum[w];
        scur[tid] = excl;
        g_starts[b * (NBINS + 1) + tid] = excl;
    }
    if (tid == 0) g_starts[b * (NBINS + 1) + NBINS] = NC;
    __syncthreads();

    // scatter from registers via smem cursors
    #pragma unroll
    for (int r = 0; r < SPT; r++) {
        int pos = atomicAdd(&scur[bin_fix(xv[r])], 1);
        g_sxy[b * NC + pos] = make_float2(xv[r], yv[r]);
    }

    // last block folds per-batch min/max partials into g_minmax
    __threadfence();
    if (tid == 0) {
        if (atomicAdd(&g_done, 1) == BATCH - 1) {
            __threadfence();
            volatile float* plo = g_plo;
            volatile float* phi = g_phi;
            float flo = INFINITY, fhi = -INFINITY;
            #pragma unroll
            for (int k = 0; k < BATCH; k++) {
                flo = fminf(flo, plo[k]); fhi = fmaxf(fhi, phi[k]);
            }
            g_minmax[0] = flo; g_minmax[1] = fhi;
            g_done = 0;
            __threadfence();
        }
    }
}

// ---------------- K2: psi stage — 4 lanes per t-point, float4 loads ----------------
__global__ void psi_kernel(const float* __restrict__ pls,
                           const float* __restrict__ pos_) {
    int g = (blockIdx.x * blockDim.x + threadIdx.x) >> 2;   // group id = t-point
    int sub = threadIdx.x & 3;
    if (g >= BATCH * TG) return;
    int b = g >> 11, i = g & (TG - 1);

    float lower = g_minmax[0], upper = g_minmax[1];
    float dt = (upper - lower) / (float)(TG - 1);
    float t = lower + i * dt;
    float ls = __ldg(pls), osv = __ldg(pos_);
    float nc2 = -0.5f * LOG2E / (ls * ls);   // exponent coefficient (base-2)
    float R = fabsf(ls) * RFAC;

    int blo = min(NBINS - 1, max(0, (int)floorf(t - R)));
    int bhi = min(NBINS - 1, max(0, (int)floorf(t + R)));
    int s = g_starts[b * (NBINS + 1) + blo];
    int e = g_starts[b * (NBINS + 1) + bhi + 1];

    // pair-granular window [ps/2, pe/2]; expanded points are exact
    // contributions (reference sums all points), and stay in-bounds:
    // pe = (e-1)&~1 covers index e only when e is odd (<= NC-1).
    int j0 = (s >> 1) + sub;
    int j1 = (e - 1) >> 1;
    const float4* sp4 = reinterpret_cast<const float4*>(g_sxy + b * NC);
    float a00 = 0.f, a10 = 0.f, a01 = 0.f, a11 = 0.f;
    for (int j = j0; j <= j1; j += 4) {
        float4 p = __ldg(&sp4[j]);
        float d0 = t - p.x;
        float d1 = t - p.z;
        float e0 = ex2(d0 * d0 * nc2);
        float e1 = ex2(d1 * d1 * nc2);
        a00 += e0; a10 = fmaf(e0, p.y, a10);
        a01 += e1; a11 = fmaf(e1, p.w, a11);
    }
    float a0 = a00 + a01, a1 = a10 + a11;
    #pragma unroll
    for (int off = 2; off; off >>= 1) {
        a0 += __shfl_xor_sync(0xffffffffu, a0, off);
        a1 += __shfl_xor_sync(0xffffffffu, a1, off);
    }
    if (sub == 0) {
        a0 *= osv; a1 *= osv;
        g_h[g] = make_float2(a0, a1 / (a0 + EPS));
    }
}

// ---------------- K3: fused 4-layer conv chain (P=4 x Q=4 register-blocked) ----------------
#define T_TILE 128
#define HALO   8
#define CW     (T_TILE + 2 * HALO)  // 144
#define CWP    152                  // padded row stride (floats), mult of 4
#define CNTH   256

// dynamic smem layout (floats), all offsets multiples of 4 (16B aligned)
#define OFF_S0  0
#define OFF_S1  (OFF_S0 + 3 * CWP)     // 456
#define OFF_S2  (OFF_S1 + 16 * CWP)    // 2888
#define OFF_W1  (OFF_S2 + 32 * CWP)    // 7752
#define OFF_W2  (OFF_W1 + 240)         // 7992
#define OFF_W3  (OFF_W2 + 2560)        // 10552
#define OFF_W4  (OFF_W3 + 2560)        // 13112
#define OFF_B1  (OFF_W4 + 160)         // 13272
#define OFF_B2  (OFF_B1 + 16)
#define OFF_B3  (OFF_B2 + 32)
#define OFF_B4  (OFF_B3 + 16)
#define SMEM_FLOATS (OFF_B4 + 4)
#define SMEM_BYTES  (SMEM_FLOATS * 4)

template <int NCO, int NCI, int LO>
__device__ __forceinline__ void conv_layer(const float* __restrict__ sin,
                                           float* __restrict__ sout,
                                           const float4* __restrict__ sw4,
                                           const float* __restrict__ sb,
                                           int p0, int tid) {
    constexpr int nv = CW - 2 * LO;         // 140 / 136 / 132 (all % 4 == 0)
    constexpr int ngp = nv / 4;
    constexpr int ncog = NCO / 4;
    constexpr int off = (LO - 2) & 3;       // 0 / 2 / 0

    for (int task = tid; task < ncog * ngp; task += CNTH) {
        int gp = task % ngp;
        int cog = task / ngp;
        int u0 = LO + gp * 4;
        int base = u0 - 2 - off;            // 16B aligned, >= 0

        float acc[4][4];
        #pragma unroll
        for (int q = 0; q < 4; q++)
            #pragma unroll
            for (int j = 0; j < 4; j++) acc[q][j] = 0.f;

        for (int ci = 0; ci < NCI; ci++) {
            const float4* sr = reinterpret_cast<const float4*>(sin + ci * CWP + base);
            float4 A = sr[0], B = sr[1], C = sr[2];
            float win[12] = {A.x, A.y, A.z, A.w, B.x, B.y, B.z, B.w,
                             C.x, C.y, C.z, C.w};
            #pragma unroll
            for (int k = 0; k < 5; k++) {
                float4 wv = sw4[(cog * NCI + ci) * 5 + k];
                #pragma unroll
                for (int j = 0; j < 4; j++) {
                    float xv = win[off + k + j];
                    acc[0][j] = fmaf(wv.x, xv, acc[0][j]);
                    acc[1][j] = fmaf(wv.y, xv, acc[1][j]);
                    acc[2][j] = fmaf(wv.z, xv, acc[2][j]);
                    acc[3][j] = fmaf(wv.w, xv, acc[3][j]);
                }
            }
        }
        #pragma unroll
        for (int q = 0; q < 4; q++) {
            int co = cog * 4 + q;
            float bias = sb[co];
            float v[4];
            #pragma unroll
            for (int j = 0; j < 4; j++) {
                int p = p0 + u0 + j;
                v[j] = (p >= 0 && p < TG) ? fmaxf(acc[q][j] + bias, 0.f) : 0.f;
            }
            float2* so = reinterpret_cast<float2*>(sout + co * CWP + u0);
            so[0] = make_float2(v[0], v[1]);
            so[1] = make_float2(v[2], v[3]);
        }
    }
}

__global__ __launch_bounds__(CNTH) void conv_kernel(
    const float* __restrict__ w1, const float* __restrict__ b1,
    const float* __restrict__ w2, const float* __restrict__ b2,
    const float* __restrict__ w3, const float* __restrict__ b3,
    const float* __restrict__ w4, const float* __restrict__ b4) {
    extern __shared__ float dsm[];
    float* s0 = dsm + OFF_S0;
    float* s1 = dsm + OFF_S1;
    float* s2 = dsm + OFF_S2;

    const int tiles = TG / T_TILE;  // 16
    int b = blockIdx.x / tiles;
    int tile = blockIdx.x % tiles;
    int p0 = tile * T_TILE - HALO;
    int tid = threadIdx.x;

    // stage weights, re-packed to [cog][ci][k][coq] so a thread's 4 co-weights
    // are a single broadcast LDS.128
    for (int i = tid; i < 240; i += CNTH) {   // w1: NCI=3 -> per-cog 60
        int co = i / 15, r = i % 15;
        dsm[OFF_W1 + (co >> 2) * 60 + r * 4 + (co & 3)] = __ldg(&w1[i]);
    }
    for (int i = tid; i < 2560; i += CNTH) {  // w2: NCI=16 -> per-cog 320
        int co = i / 80, r = i % 80;
        dsm[OFF_W2 + (co >> 2) * 320 + r * 4 + (co & 3)] = __ldg(&w2[i]);
    }
    for (int i = tid; i < 2560; i += CNTH) {  // w3: NCI=32 -> per-cog 640
        int co = i / 160, r = i % 160;
        dsm[OFF_W3 + (co >> 2) * 640 + r * 4 + (co & 3)] = __ldg(&w3[i]);
    }
    for (int i = tid; i < 160; i += CNTH)  dsm[OFF_W4 + i] = __ldg(&w4[i]);  // plain
    if (tid < 16) dsm[OFF_B1 + tid] = __ldg(&b1[tid]);
    if (tid < 32) dsm[OFF_B2 + tid] = __ldg(&b2[tid]);
    if (tid >= 32 && tid < 48) dsm[OFF_B3 + tid - 32] = __ldg(&b3[tid - 32]);
    if (tid >= 48 && tid < 50) dsm[OFF_B4 + tid - 48] = __ldg(&b4[tid - 48]);

    float lower = g_minmax[0];
    float dt = (g_minmax[1] - lower) / (float)(TG - 1);

    // load input channels (t, h0, h1); zero outside [0, TG)
    for (int u = tid; u < CW; u += CNTH) {
        int p = p0 + u;
        bool in = (p >= 0 && p < TG);
        float2 h = in ? g_h[b * TG + p] : make_float2(0.f, 0.f);
        s0[0 * CWP + u] = in ? (lower + p * dt) : 0.f;
        s0[1 * CWP + u] = h.x;
        s0[2 * CWP + u] = h.y;
    }
    __syncthreads();

    conv_layer<16, 3, 2>(s0, s1, reinterpret_cast<const float4*>(dsm + OFF_W1),
                         dsm + OFF_B1, p0, tid);
    __syncthreads();
    conv_layer<32, 16, 4>(s1, s2, reinterpret_cast<const float4*>(dsm + OFF_W2),
                          dsm + OFF_B2, p0, tid);
    __syncthreads();
    conv_layer<16, 32, 6>(s2, s1, reinterpret_cast<const float4*>(dsm + OFF_W3),
                          dsm + OFF_B3, p0, tid);
    __syncthreads();

    // layer 4: 16 -> 2; one thread per position computes BOTH channels,
    // enabling a single float2 store (and float2 loads in rho).
    if (tid < T_TILE) {
        const float* sw4 = dsm + OFF_W4;
        const float* sb4 = dsm + OFF_B4;
        int u = HALO + tid;
        float acc0 = sb4[0], acc1 = sb4[1];
        #pragma unroll
        for (int ci = 0; ci < 16; ci++) {
            #pragma unroll
            for (int k = 0; k < 5; k++) {
                float xv = s1[ci * CWP + u - 2 + k];
                acc0 = fmaf(sw4[(0 * 16 + ci) * 5 + k], xv, acc0);
                acc1 = fmaf(sw4[(1 * 16 + ci) * 5 + k], xv, acc1);
            }
        }
        int p = p0 + u;                 // always in [0, TG)
        float sp = fmaxf(acc1, 0.f) + log1pf(__expf(-fabsf(acc1)));
        g_f[b * TG + p] = make_float2(acc0, sp);
    }
}

// ---------------- K4: rho stage — 4 lanes per target, float4 loads ----------------
__global__ void rho_kernel(const float* __restrict__ xt,
                           const float* __restrict__ pls,
                           const float* __restrict__ pos_,
                           float* __restrict__ out) {
    int g = (blockIdx.x * blockDim.x + threadIdx.x) >> 2;   // group id = target
    int sub = threadIdx.x & 3;
    if (g >= BATCH * NT) return;
    int b = g >> 11;

    float lower = g_minmax[0];
    float dt = (g_minmax[1] - lower) / (float)(TG - 1);
    float inv_dt = 1.f / dt;
    float x = __ldg(&xt[g]);
    float ls = __ldg(pls), osv = __ldg(pos_);
    float nc2 = -0.5f * LOG2E / (ls * ls);
    float R = fabsf(ls) * RFAC;

    int ilo = max(0, (int)ceilf((x - R - lower) * inv_dt));
    int ihi = min(TG - 1, (int)floorf((x + R - lower) * inv_dt));

    // pair-granular window; extra grid points are exact contributions and
    // stay in-bounds (ihi even => ihi <= TG-2 => pair covers <= TG-1).
    int j0 = (ilo >> 1) + sub;
    int j1 = ihi >> 1;
    const float4* f4 = reinterpret_cast<const float4*>(g_f + b * TG);
    float mu0 = 0.f, sg0 = 0.f, mu1 = 0.f, sg1 = 0.f;
    float d0 = x - (lower + (float)(2 * j0) * dt);
    float step8 = 8.f * dt;
    for (int j = j0; j <= j1; j += 4) {
        float4 v = __ldg(&f4[j]);
        float d1 = d0 - dt;
        float e0 = ex2(d0 * d0 * nc2);
        float e1 = ex2(d1 * d1 * nc2);
        mu0 = fmaf(e0, v.x, mu0); sg0 = fmaf(e0, v.y, sg0);
        mu1 = fmaf(e1, v.z, mu1); sg1 = fmaf(e1, v.w, sg1);
        d0 -= step8;
    }
    float mu = mu0 + mu1, sg = sg0 + sg1;
    #pragma unroll
    for (int off = 2; off; off >>= 1) {
        mu += __shfl_xor_sync(0xffffffffu, mu, off);
        sg += __shfl_xor_sync(0xffffffffu, sg, off);
    }
    if (sub == 0) {
        reinterpret_cast<float2*>(out)[g] = make_float2(mu * osv, sg * osv);
    }
}

// ---------------- launch ----------------
extern "C" void kernel_launch(void* const* d_in, const int* in_sizes, int n_in,
                              void* d_out, int out_size) {
    const float* xc = (const float*)d_in[0];
    const float* yc = (const float*)d_in[1];
    const float* xt = (const float*)d_in[2];
    const float* ls_psi = (const float*)d_in[3];
    const float* os_psi = (const float*)d_in[4];
    const float* ls_rho = (const float*)d_in[5];
    const float* os_rho = (const float*)d_in[6];
    const float* w1 = (const float*)d_in[7];
    const float* b1 = (const float*)d_in[8];
    const float* w2 = (const float*)d_in[9];
    const float* b2 = (const float*)d_in[10];
    const float* w3 = (const float*)d_in[11];
    const float* b3 = (const float*)d_in[12];
    const float* w4 = (const float*)d_in[13];
    const float* b4 = (const float*)d_in[14];
    float* out = (float*)d_out;

    cudaFuncSetAttribute(conv_kernel,
                         cudaFuncAttributeMaxDynamicSharedMemorySize, SMEM_BYTES);

    sort_kernel<<<BATCH, SNTH>>>(xc, yc, xt);
    psi_kernel<<<(BATCH * TG) * 4 / 256, 256>>>(ls_psi, os_psi);
    conv_kernel<<<BATCH * (TG / T_TILE), CNTH, SMEM_BYTES>>>(w1, b1, w2, b2, w3, b3, w4, b4);
    rho_kernel<<<(BATCH * NT) * 4 / 256, 256>>>(xt, ls_rho, os_rho, out);
}

// round 11
// speedup vs baseline: 3.9827x; 1.0128x over previous
#include <cuda_runtime.h>
#include <math.h>

#define BATCH 16
#define NC    2048
#define NT    2048
#define TG    2048
#define NBINS 128
#define RFAC  3.75f    // truncation tail ~ erfc(3.75/sqrt2) = 1.8e-4 << 1e-3 gate
#define EPS   1e-8f
#define LOG2E 1.4426950408889634f

__device__ __forceinline__ float ex2(float x) {
    float y;
    asm("ex2.approx.ftz.f32 %0, %1;" : "=f"(y) : "f"(x));
    return y;
}

// Fixed binning: xc is uniform in [0, 128). Bin width = 1.0. Clamped => safe.
__device__ __forceinline__ int bin_fix(float x) {
    int b = (int)floorf(x);
    return min(NBINS - 1, max(0, b));
}

// ---------------- scratch (no allocs allowed) ----------------
__device__ float    g_minmax[2];                 // [lower, upper] (final)
__device__ float    g_plo[BATCH], g_phi[BATCH];  // per-batch partials
__device__ unsigned g_done = 0;                  // completion counter (self-resetting)
__device__ int      g_starts[BATCH * (NBINS + 1)];
__device__ __align__(16) float2 g_sxy[BATCH * NC];  // (xc, yc) sorted by bin
__device__ __align__(16) float2 g_f[BATCH * TG];    // (f_mu, softplus(f_sigma))

// ---------------- K1: fused hist + scan + scatter + minmax ----------------
#define SNTH 512
#define SPT  4   // NC / SNTH
__global__ __launch_bounds__(SNTH) void sort_kernel(
    const float* __restrict__ xc, const float* __restrict__ yc,
    const float* __restrict__ xt) {
    __shared__ int scnt[NBINS];
    __shared__ int scur[NBINS];
    __shared__ int wsum[16];
    __shared__ float slo[16], shi[16];
    int b = blockIdx.x, tid = threadIdx.x;
    int lane = tid & 31, w = tid >> 5;

    for (int i = tid; i < NBINS; i += SNTH) scnt[i] = 0;
    __syncthreads();

    const float* xcb = xc + b * NC;
    const float* ycb = yc + b * NC;
    const float* xtb = xt + b * NT;
    float xv[SPT], yv[SPT];
    float lo = INFINITY, hi = -INFINITY;
    #pragma unroll
    for (int r = 0; r < SPT; r++) {
        int i = tid + r * SNTH;
        xv[r] = __ldg(&xcb[i]);
        yv[r] = __ldg(&ycb[i]);
    }
    #pragma unroll
    for (int r = 0; r < SPT; r++) {
        lo = fminf(lo, xv[r]); hi = fmaxf(hi, xv[r]);
        atomicAdd(&scnt[bin_fix(xv[r])], 1);
    }
    #pragma unroll
    for (int r = 0; r < SPT; r++) {
        float v = __ldg(&xtb[tid + r * SNTH]);
        lo = fminf(lo, v); hi = fmaxf(hi, v);
    }
    #pragma unroll
    for (int off = 16; off; off >>= 1) {
        lo = fminf(lo, __shfl_xor_sync(0xffffffffu, lo, off));
        hi = fmaxf(hi, __shfl_xor_sync(0xffffffffu, hi, off));
    }
    if (lane == 0) { slo[w] = lo; shi[w] = hi; }
    __syncthreads();

    // exclusive scan of the 128 bin counts (threads >= 128 carry 0)
    int c = (tid < NBINS) ? scnt[tid] : 0;
    int v = c;
    #pragma unroll
    for (int off = 1; off < 32; off <<= 1) {
        int n = __shfl_up_sync(0xffffffffu, v, off);
        if (lane >= off) v += n;
    }
    if (lane == 31) wsum[w] = v;
    __syncthreads();
    if (tid == 0) {
        int run = 0;
        #pragma unroll
        for (int k = 0; k < 16; k++) { int t = wsum[k]; wsum[k] = run; run += t; }
        float flo = slo[0], fhi = shi[0];
        #pragma unroll
        for (int k = 1; k < 16; k++) { flo = fminf(flo, slo[k]); fhi = fmaxf(fhi, shi[k]); }
        g_plo[b] = flo; g_phi[b] = fhi;
    }
    __syncthreads();
    if (tid < NBINS) {
        int excl = v - c + wsum[w];
        scur[tid] = excl;
        g_starts[b * (NBINS + 1) + tid] = excl;
    }
    if (tid == 0) g_starts[b * (NBINS + 1) + NBINS] = NC;
    __syncthreads();

    // scatter from registers via smem cursors
    #pragma unroll
    for (int r = 0; r < SPT; r++) {
        int pos = atomicAdd(&scur[bin_fix(xv[r])], 1);
        g_sxy[b * NC + pos] = make_float2(xv[r], yv[r]);
    }

    // last block folds per-batch min/max partials into g_minmax
    __threadfence();
    if (tid == 0) {
        if (atomicAdd(&g_done, 1) == BATCH - 1) {
            __threadfence();
            volatile float* plo = g_plo;
            volatile float* phi = g_phi;
            float flo = INFINITY, fhi = -INFINITY;
            #pragma unroll
            for (int k = 0; k < BATCH; k++) {
                flo = fminf(flo, plo[k]); fhi = fmaxf(fhi, phi[k]);
            }
            g_minmax[0] = flo; g_minmax[1] = fhi;
            g_done = 0;
            __threadfence();
        }
    }
}

// ---------------- K2: fused psi + 4-layer conv chain ----------------
#define T_TILE 128
#define HALO   8
#define CW     (T_TILE + 2 * HALO)  // 144
#define CWP    152                  // padded row stride (floats), mult of 4
#define CNTH   256

// dynamic smem layout (floats), all offsets multiples of 4 (16B aligned)
#define OFF_S0  0
#define OFF_S1  (OFF_S0 + 3 * CWP)     // 456
#define OFF_S2  (OFF_S1 + 16 * CWP)    // 2888
#define OFF_W1  (OFF_S2 + 32 * CWP)    // 7752
#define OFF_W2  (OFF_W1 + 240)         // 7992
#define OFF_W3  (OFF_W2 + 2560)        // 10552
#define OFF_W4  (OFF_W3 + 2560)        // 13112
#define OFF_B1  (OFF_W4 + 160)         // 13272
#define OFF_B2  (OFF_B1 + 16)
#define OFF_B3  (OFF_B2 + 32)
#define OFF_B4  (OFF_B3 + 16)
#define SMEM_FLOATS (OFF_B4 + 4)
#define SMEM_BYTES  (SMEM_FLOATS * 4)

template <int NCO, int NCI, int LO>
__device__ __forceinline__ void conv_layer(const float* __restrict__ sin,
                                           float* __restrict__ sout,
                                           const float4* __restrict__ sw4,
                                           const float* __restrict__ sb,
                                           int p0, int tid) {
    constexpr int nv = CW - 2 * LO;         // 140 / 136 / 132 (all % 4 == 0)
    constexpr int ngp = nv / 4;
    constexpr int ncog = NCO / 4;
    constexpr int off = (LO - 2) & 3;       // 0 / 2 / 0

    for (int task = tid; task < ncog * ngp; task += CNTH) {
        int gp = task % ngp;
        int cog = task / ngp;
        int u0 = LO + gp * 4;
        int base = u0 - 2 - off;            // 16B aligned, >= 0

        float acc[4][4];
        #pragma unroll
        for (int q = 0; q < 4; q++)
            #pragma unroll
            for (int j = 0; j < 4; j++) acc[q][j] = 0.f;

        for (int ci = 0; ci < NCI; ci++) {
            const float4* sr = reinterpret_cast<const float4*>(sin + ci * CWP + base);
            float4 A = sr[0], B = sr[1], C = sr[2];
            float win[12] = {A.x, A.y, A.z, A.w, B.x, B.y, B.z, B.w,
                             C.x, C.y, C.z, C.w};
            #pragma unroll
            for (int k = 0; k < 5; k++) {
                float4 wv = sw4[(cog * NCI + ci) * 5 + k];
                #pragma unroll
                for (int j = 0; j < 4; j++) {
                    float xv = win[off + k + j];
                    acc[0][j] = fmaf(wv.x, xv, acc[0][j]);
                    acc[1][j] = fmaf(wv.y, xv, acc[1][j]);
                    acc[2][j] = fmaf(wv.z, xv, acc[2][j]);
                    acc[3][j] = fmaf(wv.w, xv, acc[3][j]);
                }
            }
        }
        #pragma unroll
        for (int q = 0; q < 4; q++) {
            int co = cog * 4 + q;
            float bias = sb[co];
            float v[4];
            #pragma unroll
            for (int j = 0; j < 4; j++) {
                int p = p0 + u0 + j;
                v[j] = (p >= 0 && p < TG) ? fmaxf(acc[q][j] + bias, 0.f) : 0.f;
            }
            float2* so = reinterpret_cast<float2*>(sout + co * CWP + u0);
            so[0] = make_float2(v[0], v[1]);
            so[1] = make_float2(v[2], v[3]);
        }
    }
}

__global__ __launch_bounds__(CNTH) void cnp_kernel(
    const float* __restrict__ pls, const float* __restrict__ pos_,
    const float* __restrict__ w1, const float* __restrict__ b1,
    const float* __restrict__ w2, const float* __restrict__ b2,
    const float* __restrict__ w3, const float* __restrict__ b3,
    const float* __restrict__ w4, const float* __restrict__ b4) {
    extern __shared__ float dsm[];
    float* s0 = dsm + OFF_S0;
    float* s1 = dsm + OFF_S1;
    float* s2 = dsm + OFF_S2;

    const int tiles = TG / T_TILE;  // 16
    int b = blockIdx.x / tiles;
    int tile = blockIdx.x % tiles;
    int p0 = tile * T_TILE - HALO;
    int tid = threadIdx.x;

    // stage weights, re-packed to [cog][ci][k][coq] so a thread's 4 co-weights
    // are a single broadcast LDS.128
    for (int i = tid; i < 240; i += CNTH) {   // w1: NCI=3 -> per-cog 60
        int co = i / 15, r = i % 15;
        dsm[OFF_W1 + (co >> 2) * 60 + r * 4 + (co & 3)] = __ldg(&w1[i]);
    }
    for (int i = tid; i < 2560; i += CNTH) {  // w2: NCI=16 -> per-cog 320
        int co = i / 80, r = i % 80;
        dsm[OFF_W2 + (co >> 2) * 320 + r * 4 + (co & 3)] = __ldg(&w2[i]);
    }
    for (int i = tid; i < 2560; i += CNTH) {  // w3: NCI=32 -> per-cog 640
        int co = i / 160, r = i % 160;
        dsm[OFF_W3 + (co >> 2) * 640 + r * 4 + (co & 3)] = __ldg(&w3[i]);
    }
    for (int i = tid; i < 160; i += CNTH)  dsm[OFF_W4 + i] = __ldg(&w4[i]);  // plain
    if (tid < 16) dsm[OFF_B1 + tid] = __ldg(&b1[tid]);
    if (tid < 32) dsm[OFF_B2 + tid] = __ldg(&b2[tid]);
    if (tid >= 32 && tid < 48) dsm[OFF_B3 + tid - 32] = __ldg(&b3[tid - 32]);
    if (tid >= 48 && tid < 50) dsm[OFF_B4 + tid - 48] = __ldg(&b4[tid - 48]);

    float lower = g_minmax[0], upper = g_minmax[1];
    float dt = (upper - lower) / (float)(TG - 1);

    // ---- psi phase: compute (t, h0, h1) for this block's CW positions ----
    // 4 sub-lanes per position; 576 tasks, multiple of 32 and round-aligned
    // at warp boundaries => full-warp shuffles are safe.
    {
        float ls = __ldg(pls), osv = __ldg(pos_);
        float nc2 = -0.5f * LOG2E / (ls * ls);
        float R = fabsf(ls) * RFAC;
        const int nb = b * (NBINS + 1);
        const float4* sp4 = reinterpret_cast<const float4*>(g_sxy + b * NC);

        for (int task = tid; task < CW * 4; task += CNTH) {
            int u = task >> 2, sub = task & 3;
            int p = p0 + u;
            bool in = (p >= 0 && p < TG);
            float t = lower + p * dt;
            float a00 = 0.f, a10 = 0.f, a01 = 0.f, a11 = 0.f;
            if (in) {
                int blo = min(NBINS - 1, max(0, (int)floorf(t - R)));
                int bhi = min(NBINS - 1, max(0, (int)floorf(t + R)));
                int s = g_starts[nb + blo];
                int e = g_starts[nb + bhi + 1];
                int j0 = (s >> 1) + sub;
                int j1 = (e - 1) >> 1;
                for (int j = j0; j <= j1; j += 4) {
                    float4 pt = __ldg(&sp4[j]);
                    float d0 = t - pt.x;
                    float d1 = t - pt.z;
                    float e0 = ex2(d0 * d0 * nc2);
                    float e1 = ex2(d1 * d1 * nc2);
                    a00 += e0; a10 = fmaf(e0, pt.y, a10);
                    a01 += e1; a11 = fmaf(e1, pt.w, a11);
                }
            }
            float a0 = a00 + a01, a1 = a10 + a11;
            #pragma unroll
            for (int off = 2; off; off >>= 1) {
                a0 += __shfl_xor_sync(0xffffffffu, a0, off);
                a1 += __shfl_xor_sync(0xffffffffu, a1, off);
            }
            if (sub == 0) {
                a0 *= osv; a1 *= osv;
                s0[0 * CWP + u] = in ? t : 0.f;
                s0[1 * CWP + u] = a0;                       // 0 if !in
                s0[2 * CWP + u] = in ? a1 / (a0 + EPS) : 0.f;
            }
        }
    }
    __syncthreads();

    conv_layer<16, 3, 2>(s0, s1, reinterpret_cast<const float4*>(dsm + OFF_W1),
                         dsm + OFF_B1, p0, tid);
    __syncthreads();
    conv_layer<32, 16, 4>(s1, s2, reinterpret_cast<const float4*>(dsm + OFF_W2),
                          dsm + OFF_B2, p0, tid);
    __syncthreads();
    conv_layer<16, 32, 6>(s2, s1, reinterpret_cast<const float4*>(dsm + OFF_W3),
                          dsm + OFF_B3, p0, tid);
    __syncthreads();

    // layer 4: 16 -> 2; one thread per position computes BOTH channels,
    // enabling a single float2 store (and float2 loads in rho).
    if (tid < T_TILE) {
        const float* sw4 = dsm + OFF_W4;
        const float* sb4 = dsm + OFF_B4;
        int u = HALO + tid;
        float acc0 = sb4[0], acc1 = sb4[1];
        #pragma unroll
        for (int ci = 0; ci < 16; ci++) {
            #pragma unroll
            for (int k = 0; k < 5; k++) {
                float xv = s1[ci * CWP + u - 2 + k];
                acc0 = fmaf(sw4[(0 * 16 + ci) * 5 + k], xv, acc0);
                acc1 = fmaf(sw4[(1 * 16 + ci) * 5 + k], xv, acc1);
            }
        }
        int p = p0 + u;                 // always in [0, TG)
        float sp = fmaxf(acc1, 0.f) + log1pf(__expf(-fabsf(acc1)));
        g_f[b * TG + p] = make_float2(acc0, sp);
    }
}

// ---------------- K3: rho stage — 8 lanes per target, float4 loads ----------------
__global__ void rho_kernel(const float* __restrict__ xt,
                           const float* __restrict__ pls,
                           const float* __restrict__ pos_,
                           float* __restrict__ out) {
    int g = (blockIdx.x * blockDim.x + threadIdx.x) >> 3;   // group id = target
    int sub = threadIdx.x & 7;
    if (g >= BATCH * NT) return;
    int b = g >> 11;

    float lower = g_minmax[0];
    float dt = (g_minmax[1] - lower) / (float)(TG - 1);
    float inv_dt = 1.f / dt;
    float x = __ldg(&xt[g]);
    float ls = __ldg(pls), osv = __ldg(pos_);
    float nc2 = -0.5f * LOG2E / (ls * ls);
    float R = fabsf(ls) * RFAC;

    int ilo = max(0, (int)ceilf((x - R - lower) * inv_dt));
    int ihi = min(TG - 1, (int)floorf((x + R - lower) * inv_dt));

    // pair-granular window; extra grid points are exact contributions and
    // stay in-bounds (ihi even => ihi <= TG-2 => pair covers <= TG-1).
    int j0 = (ilo >> 1) + sub;
    int j1 = ihi >> 1;
    const float4* f4 = reinterpret_cast<const float4*>(g_f + b * TG);
    float mu0 = 0.f, sg0 = 0.f, mu1 = 0.f, sg1 = 0.f;
    float d0 = x - (lower + (float)(2 * j0) * dt);
    float step16 = 16.f * dt;
    for (int j = j0; j <= j1; j += 8) {
        float4 v = __ldg(&f4[j]);
        float d1 = d0 - dt;
        float e0 = ex2(d0 * d0 * nc2);
        float e1 = ex2(d1 * d1 * nc2);
        mu0 = fmaf(e0, v.x, mu0); sg0 = fmaf(e0, v.y, sg0);
        mu1 = fmaf(e1, v.z, mu1); sg1 = fmaf(e1, v.w, sg1);
        d0 -= step16;
    }
    float mu = mu0 + mu1, sg = sg0 + sg1;
    #pragma unroll
    for (int off = 4; off; off >>= 1) {
        mu += __shfl_xor_sync(0xffffffffu, mu, off);
        sg += __shfl_xor_sync(0xffffffffu, sg, off);
    }
    if (sub == 0) {
        reinterpret_cast<float2*>(out)[g] = make_float2(mu * osv, sg * osv);
    }
}

// ---------------- launch ----------------
extern "C" void kernel_launch(void* const* d_in, const int* in_sizes, int n_in,
                              void* d_out, int out_size) {
    const float* xc = (const float*)d_in[0];
    const float* yc = (const float*)d_in[1];
    const float* xt = (const float*)d_in[2];
    const float* ls_psi = (const float*)d_in[3];
    const float* os_psi = (const float*)d_in[4];
    const float* ls_rho = (const float*)d_in[5];
    const float* os_rho = (const float*)d_in[6];
    const float* w1 = (const float*)d_in[7];
    const float* b1 = (const float*)d_in[8];
    const float* w2 = (const float*)d_in[9];
    const float* b2 = (const float*)d_in[10];
    const float* w3 = (const float*)d_in[11];
    const float* b3 = (const float*)d_in[12];
    const float* w4 = (const float*)d_in[13];
    const float* b4 = (const float*)d_in[14];
    float* out = (float*)d_out;

    cudaFuncSetAttribute(cnp_kernel,
                         cudaFuncAttributeMaxDynamicSharedMemorySize, SMEM_BYTES);

    sort_kernel<<<BATCH, SNTH>>>(xc, yc, xt);
    cnp_kernel<<<BATCH * (TG / T_TILE), CNTH, SMEM_BYTES>>>(
        ls_psi, os_psi, w1, b1, w2, b2, w3, b3, w4, b4);
    rho_kernel<<<(BATCH * NT) * 8 / 256, 256>>>(xt, ls_rho, os_rho, out);
}